// round 10
// baseline (speedup 1.0000x reference)
#include <cuda_runtime.h>
#include <cstdint>

#define B_   4
#define N_   16384
#define C_   64
#define S_   2048
#define K_   32
#define M_   (B_*S_*K_)
#define CO_  128
#define KP0_ 72

#define PACK_F32X2(out, lo, hi) \
    asm("mov.b64 %0, {%1, %2};" : "=l"(out) : "f"(lo), "f"(hi))
#define UNPACK_F32X2(lo, hi, in) \
    asm("mov.b64 {%0, %1}, %2;" : "=f"(lo), "=f"(hi) : "l"(in))
#define ADD_F32X2(out, a, b) \
    asm("add.rn.f32x2 %0, %1, %2;" : "=l"(out) : "l"(a), "l"(b))
#define MUL_F32X2(out, a, b) \
    asm("mul.rn.f32x2 %0, %1, %2;" : "=l"(out) : "l"(a), "l"(b))
#define FMA_F32X2(out, a, b, c) \
    asm("fma.rn.f32x2 %0, %1, %2, %3;" : "=l"(out) : "l"(a), "l"(b), "l"(c))

typedef unsigned long long u64;

__device__ __align__(16) float g_newxyz[B_*S_*3];
__device__ int   g_idx[B_*S_*K_];
__device__ __align__(16) float g_ptsT[(size_t)B_*N_*C_];
__device__ float g_pnorm[B_*N_];
__device__ __align__(16) float g_Ybuf[(size_t)M_*CO_];
__device__ __align__(16) float g_Xbuf[(size_t)M_*CO_];
__device__ __align__(16) float g_Hbuf[(size_t)M_*CO_];
__device__ __align__(16) float g_Zbuf[(size_t)M_*CO_];
__device__ __align__(16) float g_Wp[CO_*KP0_];
__device__ __align__(16) float g_sum[CO_];
__device__ __align__(16) float g_sq[CO_];
__device__ __align__(16) float g_scaleL[5*CO_];
__device__ __align__(16) float g_shiftL[5*CO_];

__global__ void transpose_pts(const float* __restrict__ pts){
    __shared__ float tile[32][33];
    int b=blockIdx.z, n0=blockIdx.x<<5, c0=blockIdx.y<<5;
    int tx=threadIdx.x, ty=threadIdx.y;
    tile[ty][tx]=pts[((size_t)b*C_+(c0+ty))*N_+n0+tx];
    __syncthreads();
    g_ptsT[((size_t)b*N_+(n0+ty))*C_+c0+tx]=tile[tx][ty];
}

__global__ void pnorm_kernel(const float* __restrict__ xyz){
    int id=blockIdx.x*blockDim.x+threadIdx.x;
    if(id>=B_*N_) return;
    int b=id/N_, n=id%N_;
    const float* Xp=xyz+(size_t)b*3*N_;
    float x=Xp[n], y=Xp[N_+n], z=Xp[2*N_+n];
    g_pnorm[id]=fmaf(z,z,fmaf(x,x,y*y));
}

__global__ void wpad_kernel(const float* __restrict__ w){
    int id=blockIdx.x*blockDim.x+threadIdx.x;
    if(id>=CO_*KP0_) return;
    int o=id/KP0_, k=id%KP0_;
    g_Wp[id]=(k<67)?w[o*67+k]:0.0f;
}

__global__ void __launch_bounds__(512,1) fps_kernel(const float* __restrict__ xyz,
                                                    float* __restrict__ out0){
    extern __shared__ u64 fsmu[];
    const int b=blockIdx.x, t=threadIdx.x;
    const float* Xp=xyz+(size_t)b*3*N_;
    u64* sxu=fsmu;
    u64* syu=fsmu+8192;
    u64* szu=fsmu+16384;
    __shared__ int s_bmax[2];
    __shared__ int s_win[2];

    u64 rx[8], ry[8], rz[8];
    float dmin[32];
#pragma unroll
    for(int j=0;j<16;j++){
        int n=j*512+t;
        float x0=Xp[n],        x1=Xp[n+8192];
        float y0=Xp[N_+n],     y1=Xp[N_+n+8192];
        float z0=Xp[2*N_+n],   z1=Xp[2*N_+n+8192];
        u64 px,py,pz;
        PACK_F32X2(px,x0,x1); PACK_F32X2(py,y0,y1); PACK_F32X2(pz,z0,z1);
        sxu[n]=px; syu[n]=py; szu[n]=pz;
        if(j<8){ rx[j]=px; ry[j]=py; rz[j]=pz; }
        dmin[2*j]=1e10f; dmin[2*j+1]=1e10f;
    }
    float cx=Xp[0], cy=Xp[N_], cz=Xp[2*N_];
    if(t==0){
        out0[(size_t)b*3*S_+0]      =cx;
        out0[(size_t)b*3*S_+S_+0]   =cy;
        out0[(size_t)b*3*S_+2*S_+0] =cz;
        float* nz=g_newxyz+(size_t)b*S_*3;
        nz[0]=cx; nz[1]=cy; nz[2]=cz;
        s_bmax[0]=0; s_bmax[1]=0;
        s_win[0]=0x7fffffff; s_win[1]=0x7fffffff;
    }
    __syncthreads();

    const int lane=t&31;
    int p=0;
    for(int it=0; it<S_-1; ++it){
        float ncx=-cx, ncy=-cy, ncz=-cz;
        u64 ncx2,ncy2,ncz2;
        PACK_F32X2(ncx2,ncx,ncx); PACK_F32X2(ncy2,ncy,ncy); PACK_F32X2(ncz2,ncz,ncz);
        float bv=0.0f;
#pragma unroll
        for(int j=0;j<8;j++){
            u64 dx,dy,dz,tt,dd;
            ADD_F32X2(dx,rx[j],ncx2);
            ADD_F32X2(dy,ry[j],ncy2);
            ADD_F32X2(dz,rz[j],ncz2);
            MUL_F32X2(tt,dy,dy);
            FMA_F32X2(tt,dx,dx,tt);
            FMA_F32X2(dd,dz,dz,tt);
            float d0,d1; UNPACK_F32X2(d0,d1,dd);
            float m0=fminf(dmin[2*j],d0);   dmin[2*j]=m0;
            float m1=fminf(dmin[2*j+1],d1); dmin[2*j+1]=m1;
            bv=fmaxf(bv,m0); bv=fmaxf(bv,m1);
        }
#pragma unroll
        for(int j=8;j<16;j++){
            int n=j*512+t;
            u64 dx,dy,dz,tt,dd;
            ADD_F32X2(dx,sxu[n],ncx2);
            ADD_F32X2(dy,syu[n],ncy2);
            ADD_F32X2(dz,szu[n],ncz2);
            MUL_F32X2(tt,dy,dy);
            FMA_F32X2(tt,dx,dx,tt);
            FMA_F32X2(dd,dz,dz,tt);
            float d0,d1; UNPACK_F32X2(d0,d1,dd);
            float m0=fminf(dmin[2*j],d0);   dmin[2*j]=m0;
            float m1=fminf(dmin[2*j+1],d1); dmin[2*j+1]=m1;
            bv=fmaxf(bv,m0); bv=fmaxf(bv,m1);
        }
#pragma unroll
        for(int off=16; off>0; off>>=1)
            bv=fmaxf(bv,__shfl_xor_sync(0xffffffffu,bv,off));
        if(lane==0) atomicMax(&s_bmax[p], __float_as_int(bv));
        __syncthreads();
        const float bmax=__int_as_float(s_bmax[p]);
        if(bv==bmax){
            int cand=0x7fffffff;
#pragma unroll
            for(int k=0;k<32;k++){
                int idx=(k>>1)*512+t+((k&1)<<13);
                if(dmin[k]==bmax) cand=min(cand,idx);
            }
#pragma unroll
            for(int off=16; off>0; off>>=1)
                cand=min(cand,__shfl_xor_sync(0xffffffffu,cand,off));
            if(lane==0) atomicMin(&s_win[p],cand);
        }
        __syncthreads();
        const int w=s_win[p];
        int n=w&8191, hi=w>>13;
        float a0,a1;
        UNPACK_F32X2(a0,a1,sxu[n]); cx = hi? a1:a0;
        UNPACK_F32X2(a0,a1,syu[n]); cy = hi? a1:a0;
        UNPACK_F32X2(a0,a1,szu[n]); cz = hi? a1:a0;
        if(t==0){ s_bmax[p^1]=0; s_win[p^1]=0x7fffffff; }
        if(t==32){
            out0[(size_t)b*3*S_+(it+1)]       =cx;
            out0[(size_t)b*3*S_+S_+(it+1)]    =cy;
            out0[(size_t)b*3*S_+2*S_+(it+1)]  =cz;
            float* nz=g_newxyz+((size_t)b*S_+(it+1))*3;
            nz[0]=cx; nz[1]=cy; nz[2]=cz;
        }
        p^=1;
    }
}

__global__ void query_kernel(const float* __restrict__ xyz){
    int gw=(blockIdx.x*blockDim.x+threadIdx.x)>>5;
    int lane=threadIdx.x&31;
    if(gw>=B_*S_) return;
    int b=gw/S_;
    const float* nz=g_newxyz+(size_t)gw*3;
    float cx=nz[0],cy=nz[1],cz=nz[2];
    float srcn=fmaf(cz,cz,fmaf(cx,cx,cy*cy));
    const float* Xp=xyz+(size_t)b*3*N_;
    const float* pn=g_pnorm+(size_t)b*N_;
    int* dst=g_idx+(size_t)gw*K_;
    int count=0, first=0; bool haveFirst=false;
    for(int base=0; base<N_; base+=32){
        int n=base+lane;
        float dot=fmaf(cz,Xp[2*N_+n],fmaf(cy,Xp[N_+n],cx*Xp[n]));
        float d=fmaf(-2.0f,dot,srcn)+pn[n];
        bool ok=!(d>0.04f);
        unsigned m=__ballot_sync(0xffffffffu,ok);
        if(m){
            if(!haveFirst){first=base+__ffs(m)-1; haveFirst=true;}
            int rank=__popc(m&((1u<<lane)-1u));
            if(ok&&(count+rank)<K_) dst[count+rank]=n;
            count+=__popc(m);
            if(count>=K_) break;
        }
    }
    if(count<K_){
        for(int sl=count+lane; sl<K_; sl+=32) dst[sl]=first;
    }
}

// MODE: 0=raw A, 1=bn+relu on A, 2=gather-build A (proj),
//       3=A = relu(bnA(a) + relu(bnB(a0)))
// FFMA2 microkernel: acc packed over row pairs; B stored duplicated {w,w} in SMEM.
template<int K, int MODE>
__global__ void __launch_bounds__(256,2) gemm_kernel(const float* __restrict__ A,
                                                     const float* __restrict__ W,
                                                     float* __restrict__ Y,
                                                     const float* __restrict__ xyz,
                                                     const float* __restrict__ scA,
                                                     const float* __restrict__ shA,
                                                     const float* __restrict__ A0,
                                                     const float* __restrict__ scB,
                                                     const float* __restrict__ shB){
    __shared__ float As[2][8][128];
    __shared__ u64   Bsd[2][8][128];   // duplicated {w,w}
    const int tid=threadIdx.x, m0=blockIdx.x<<7;
    const int tm=tid>>4, tn=tid&15;
    const int lrow=tid>>1, lcol=(tid&1)<<2;
    const int row=m0+lrow;

    const float* gsrc=nullptr; const float* xp=nullptr;
    float ncx=0.f,ncy=0.f,ncz=0.f; int jj=0;
    if(MODE==2){
        jj=g_idx[row];
        int bidx=row>>16;
        int cent=row>>5;
        ncx=g_newxyz[cent*3+0]; ncy=g_newxyz[cent*3+1]; ncz=g_newxyz[cent*3+2];
        gsrc=g_ptsT+((size_t)bidx*N_+jj)*C_;
        xp=xyz+(size_t)bidx*3*N_;
    }
    const float* Aptr=A+(size_t)row*K+lcol;
    const float* A0ptr=(MODE==3)? A0+(size_t)row*K+lcol : nullptr;
    const float* Wptr=W+(size_t)lrow*K+lcol;

    auto loadA=[&](int k0)->float4{
        if(MODE==2){
            float v[4];
#pragma unroll
            for(int q=0;q<4;q++){
                int c=k0+lcol+q;
                float t;
                if(c<3){ float nn=(c==0)?ncx:((c==1)?ncy:ncz); t=xp[(size_t)c*N_+jj]-nn; }
                else if(c<67) t=gsrc[c-3];
                else t=0.f;
                v[q]=t;
            }
            return make_float4(v[0],v[1],v[2],v[3]);
        }else{
            float4 a=*reinterpret_cast<const float4*>(Aptr+k0);
            if(MODE==1){
                int c=k0+lcol;
                float4 sc=*reinterpret_cast<const float4*>(&scA[c]);
                float4 sh=*reinterpret_cast<const float4*>(&shA[c]);
                a.x=fmaxf(0.f,fmaf(a.x,sc.x,sh.x));
                a.y=fmaxf(0.f,fmaf(a.y,sc.y,sh.y));
                a.z=fmaxf(0.f,fmaf(a.z,sc.z,sh.z));
                a.w=fmaxf(0.f,fmaf(a.w,sc.w,sh.w));
            }else if(MODE==3){
                int c=k0+lcol;
                float4 a0=*reinterpret_cast<const float4*>(A0ptr+k0);
                float4 sc=*reinterpret_cast<const float4*>(&scA[c]);
                float4 sh=*reinterpret_cast<const float4*>(&shA[c]);
                float4 s0=*reinterpret_cast<const float4*>(&scB[c]);
                float4 h0=*reinterpret_cast<const float4*>(&shB[c]);
                float x0=fmaxf(0.f,fmaf(a0.x,s0.x,h0.x));
                float x1=fmaxf(0.f,fmaf(a0.y,s0.y,h0.y));
                float x2=fmaxf(0.f,fmaf(a0.z,s0.z,h0.z));
                float x3=fmaxf(0.f,fmaf(a0.w,s0.w,h0.w));
                a.x=fmaxf(0.f,fmaf(a.x,sc.x,sh.x)+x0);
                a.y=fmaxf(0.f,fmaf(a.y,sc.y,sh.y)+x1);
                a.z=fmaxf(0.f,fmaf(a.z,sc.z,sh.z)+x2);
                a.w=fmaxf(0.f,fmaf(a.w,sc.w,sh.w)+x3);
            }
            return a;
        }
    };

    auto stageB=[&](int buf, float4 wv){
        u64 u0,u1,u2,u3;
        PACK_F32X2(u0,wv.x,wv.x); PACK_F32X2(u1,wv.y,wv.y);
        PACK_F32X2(u2,wv.z,wv.z); PACK_F32X2(u3,wv.w,wv.w);
        Bsd[buf][lcol+0][lrow]=u0; Bsd[buf][lcol+1][lrow]=u1;
        Bsd[buf][lcol+2][lrow]=u2; Bsd[buf][lcol+3][lrow]=u3;
    };

    u64 acc2[4][8];
#pragma unroll
    for(int i=0;i<4;i++)
#pragma unroll
        for(int j=0;j<8;j++) acc2[i][j]=0ull;

    constexpr int NT=K/8;
    float4 av=loadA(0);
    float4 wv=*reinterpret_cast<const float4*>(Wptr);
    As[0][lcol+0][lrow]=av.x; As[0][lcol+1][lrow]=av.y; As[0][lcol+2][lrow]=av.z; As[0][lcol+3][lrow]=av.w;
    stageB(0,wv);
    __syncthreads();

    for(int it=0; it<NT; ++it){
        const int cur=it&1;
        if(it+1<NT){
            av=loadA((it+1)*8);
            wv=*reinterpret_cast<const float4*>(Wptr+(it+1)*8);
        }
#pragma unroll
        for(int kk=0;kk<8;kk++){
            const u64* arow=reinterpret_cast<const u64*>(&As[cur][kk][tm<<3]);
            ulonglong2 aa0=*reinterpret_cast<const ulonglong2*>(arow);
            ulonglong2 aa1=*reinterpret_cast<const ulonglong2*>(arow+2);
            u64 a2[4]={aa0.x,aa0.y,aa1.x,aa1.y};
            const u64* wrow=&Bsd[cur][kk][tn<<3];
            ulonglong2 ww0=*reinterpret_cast<const ulonglong2*>(wrow);
            ulonglong2 ww1=*reinterpret_cast<const ulonglong2*>(wrow+2);
            ulonglong2 ww2=*reinterpret_cast<const ulonglong2*>(wrow+4);
            ulonglong2 ww3=*reinterpret_cast<const ulonglong2*>(wrow+6);
            u64 w2[8]={ww0.x,ww0.y,ww1.x,ww1.y,ww2.x,ww2.y,ww3.x,ww3.y};
#pragma unroll
            for(int i=0;i<4;i++)
#pragma unroll
                for(int j=0;j<8;j++)
                    FMA_F32X2(acc2[i][j], a2[i], w2[j], acc2[i][j]);
        }
        if(it+1<NT){
            const int nxt=cur^1;
            As[nxt][lcol+0][lrow]=av.x; As[nxt][lcol+1][lrow]=av.y; As[nxt][lcol+2][lrow]=av.z; As[nxt][lcol+3][lrow]=av.w;
            stageB(nxt,wv);
        }
        __syncthreads();
    }

    // epilogue: unpack two rows at a time; store + per-column stats
    float cs[8], cq[8];
#pragma unroll
    for(int j=0;j<8;j++){ cs[j]=0.f; cq[j]=0.f; }
#pragma unroll
    for(int i2=0;i2<4;i2++){
        float lo[8], hi[8];
#pragma unroll
        for(int j=0;j<8;j++){
            UNPACK_F32X2(lo[j],hi[j],acc2[i2][j]);
            cs[j]+=lo[j]; cq[j]=fmaf(lo[j],lo[j],cq[j]);
            cs[j]+=hi[j]; cq[j]=fmaf(hi[j],hi[j],cq[j]);
        }
        float* yp0=Y+(size_t)(m0+(tm<<3)+2*i2)*CO_+(tn<<3);
        float* yp1=Y+(size_t)(m0+(tm<<3)+2*i2+1)*CO_+(tn<<3);
        *reinterpret_cast<float4*>(yp0)  =make_float4(lo[0],lo[1],lo[2],lo[3]);
        *reinterpret_cast<float4*>(yp0+4)=make_float4(lo[4],lo[5],lo[6],lo[7]);
        *reinterpret_cast<float4*>(yp1)  =make_float4(hi[0],hi[1],hi[2],hi[3]);
        *reinterpret_cast<float4*>(yp1+4)=make_float4(hi[4],hi[5],hi[6],hi[7]);
    }

    float* ss=&As[0][0][0];
#pragma unroll
    for(int j=0;j<8;j++) ss[tm*128 + (tn<<3)+j]=cs[j];
    __syncthreads();
    if(tid<128){
        float s=0.f;
#pragma unroll
        for(int t=0;t<16;t++) s+=ss[t*128+tid];
        atomicAdd(&g_sum[tid], s);
    }
    __syncthreads();
#pragma unroll
    for(int j=0;j<8;j++) ss[tm*128 + (tn<<3)+j]=cq[j];
    __syncthreads();
    if(tid<128){
        float s=0.f;
#pragma unroll
        for(int t=0;t<16;t++) s+=ss[t*128+tid];
        atomicAdd(&g_sq[tid], s);
    }
}

__global__ void stats_zero(){
    int c=threadIdx.x;
    if(c<CO_){g_sum[c]=0.f; g_sq[c]=0.f;}
}

__global__ void finalize_kernel(const float* __restrict__ gg, const float* __restrict__ bb,
                                float* __restrict__ sc_out, float* __restrict__ sh_out){
    int c=threadIdx.x;
    if(c<CO_){
        const float inv=1.0f/(float)M_;
        float mu=g_sum[c]*inv;
        float var=g_sq[c]*inv-mu*mu;
        float rs=rsqrtf(var+1e-5f);
        float sc=gg[c]*rs;
        sc_out[c]=sc;
        sh_out[c]=bb[c]-mu*sc;
        g_sum[c]=0.f; g_sq[c]=0.f;
    }
}

__global__ void maxpool3_kernel(const float* __restrict__ Y4, const float* __restrict__ Y2,
                                const float* __restrict__ Y0, float* __restrict__ out2,
                                const float* __restrict__ scL, const float* __restrict__ shL){
    int id=blockIdx.x*blockDim.x+threadIdx.x;
    int c=id&127;
    int s=(id>>7)&(S_-1);
    int b=id>>18;
    size_t base=((size_t)(b*S_+s)*K_)*CO_+c;
    float sc0=scL[0*CO_+c], sh0=shL[0*CO_+c];
    float sc2=scL[2*CO_+c], sh2=shL[2*CO_+c];
    float sc4=scL[4*CO_+c], sh4=shL[4*CO_+c];
    float m=-1e30f;
#pragma unroll
    for(int k=0;k<K_;k++){
        size_t o=base+(size_t)k*CO_;
        float x0=fmaxf(0.f,fmaf(Y0[o],sc0,sh0));
        float xr=fmaxf(0.f,fmaf(Y2[o],sc2,sh2)+x0);
        float v =fmaxf(0.f,fmaf(Y4[o],sc4,sh4)+xr);
        m=fmaxf(m,v);
    }
    out2[((size_t)b*CO_+c)*S_+s]=m;
}

extern "C" void kernel_launch(void* const* d_in, const int* in_sizes, int n_in,
                              void* d_out, int out_size){
    const float* xyz  =(const float*)d_in[0];
    const float* pts  =(const float*)d_in[1];
    const float* wproj=(const float*)d_in[2];
    const float* gproj=(const float*)d_in[3];
    const float* bproj=(const float*)d_in[4];
    const float* w1   =(const float*)d_in[5];
    const float* w2   =(const float*)d_in[6];
    const float* g1   =(const float*)d_in[7];
    const float* b1   =(const float*)d_in[8];
    const float* g2   =(const float*)d_in[9];
    const float* b2   =(const float*)d_in[10];
    float* out=(float*)d_out;

    void *pYv,*pXv,*pHv,*pZv,*pWpv,*pScv,*pShv;
    cudaGetSymbolAddress(&pYv, g_Ybuf);
    cudaGetSymbolAddress(&pXv, g_Xbuf);
    cudaGetSymbolAddress(&pHv, g_Hbuf);
    cudaGetSymbolAddress(&pZv, g_Zbuf);
    cudaGetSymbolAddress(&pWpv,g_Wp);
    cudaGetSymbolAddress(&pScv,g_scaleL);
    cudaGetSymbolAddress(&pShv,g_shiftL);
    float* pY=(float*)pYv; float* pX=(float*)pXv; float* pH=(float*)pHv;
    float* pZ=(float*)pZv; float* pWp=(float*)pWpv;
    float* scL=(float*)pScv; float* shL=(float*)pShv;

    cudaFuncSetAttribute(fps_kernel, cudaFuncAttributeMaxDynamicSharedMemorySize, 3*8192*8);

    transpose_pts<<<dim3(N_/32, C_/32, B_), dim3(32,32)>>>(pts);
    pnorm_kernel<<<(B_*N_+1023)/1024,1024>>>(xyz);
    wpad_kernel<<<(CO_*KP0_+1023)/1024,1024>>>(wproj);

    fps_kernel<<<B_,512,3*8192*8>>>(xyz,out);
    query_kernel<<<(B_*S_*32)/256,256>>>(xyz);

    const int GG=M_/128;
    stats_zero<<<1,128>>>();

    gemm_kernel<KP0_,2><<<GG,256>>>(pY, pWp, pY, xyz, scL, shL, nullptr, nullptr, nullptr);
    finalize_kernel<<<1,128>>>(gproj, bproj, scL+0*CO_, shL+0*CO_);

    gemm_kernel<128,1><<<GG,256>>>(pY, w1, pH, xyz, scL+0*CO_, shL+0*CO_, nullptr, nullptr, nullptr);
    finalize_kernel<<<1,128>>>(g1, b1, scL+1*CO_, shL+1*CO_);
    gemm_kernel<128,1><<<GG,256>>>(pH, w2, pX, xyz, scL+1*CO_, shL+1*CO_, nullptr, nullptr, nullptr);
    finalize_kernel<<<1,128>>>(g2, b2, scL+2*CO_, shL+2*CO_);

    gemm_kernel<128,3><<<GG,256>>>(pX, w1+CO_*CO_, pZ, xyz,
                                   scL+2*CO_, shL+2*CO_, pY, scL+0*CO_, shL+0*CO_);
    finalize_kernel<<<1,128>>>(g1+CO_, b1+CO_, scL+3*CO_, shL+3*CO_);
    gemm_kernel<128,1><<<GG,256>>>(pZ, w2+CO_*CO_, pH, xyz, scL+3*CO_, shL+3*CO_, nullptr, nullptr, nullptr);
    finalize_kernel<<<1,128>>>(g2+CO_, b2+CO_, scL+4*CO_, shL+4*CO_);

    maxpool3_kernel<<<(B_*S_*CO_)/256,256>>>(pH, pX, pY, out + B_*3*S_, scL, shL);
}

// round 11
// speedup vs baseline: 1.3984x; 1.3984x over previous
#include <cuda_runtime.h>
#include <cstdint>

#define B_   4
#define N_   16384
#define C_   64
#define S_   2048
#define K_   32
#define M_   (B_*S_*K_)
#define CO_  128
#define KP0_ 72

#define PACK_F32X2(out, lo, hi) \
    asm("mov.b64 %0, {%1, %2};" : "=l"(out) : "f"(lo), "f"(hi))
#define UNPACK_F32X2(lo, hi, in) \
    asm("mov.b64 {%0, %1}, %2;" : "=f"(lo), "=f"(hi) : "l"(in))
#define ADD_F32X2(out, a, b) \
    asm("add.rn.f32x2 %0, %1, %2;" : "=l"(out) : "l"(a), "l"(b))
#define MUL_F32X2(out, a, b) \
    asm("mul.rn.f32x2 %0, %1, %2;" : "=l"(out) : "l"(a), "l"(b))
#define FMA_F32X2(out, a, b, c) \
    asm("fma.rn.f32x2 %0, %1, %2, %3;" : "=l"(out) : "l"(a), "l"(b), "l"(c))

typedef unsigned long long u64;

__device__ __align__(16) float g_newxyz[B_*S_*3];
__device__ int   g_idx[B_*S_*K_];
__device__ __align__(16) float g_ptsT[(size_t)B_*N_*C_];
__device__ float g_pnorm[B_*N_];
__device__ __align__(16) float g_Ybuf[(size_t)M_*CO_];
__device__ __align__(16) float g_Xbuf[(size_t)M_*CO_];
__device__ __align__(16) float g_Hbuf[(size_t)M_*CO_];
__device__ __align__(16) float g_Zbuf[(size_t)M_*CO_];
__device__ __align__(16) float g_Wp[CO_*KP0_];
__device__ __align__(16) float g_sum[CO_];
__device__ __align__(16) float g_sq[CO_];
__device__ __align__(16) float g_scaleL[5*CO_];
__device__ __align__(16) float g_shiftL[5*CO_];

__global__ void transpose_pts(const float* __restrict__ pts){
    __shared__ float tile[32][33];
    int b=blockIdx.z, n0=blockIdx.x<<5, c0=blockIdx.y<<5;
    int tx=threadIdx.x, ty=threadIdx.y;
    tile[ty][tx]=pts[((size_t)b*C_+(c0+ty))*N_+n0+tx];
    __syncthreads();
    g_ptsT[((size_t)b*N_+(n0+ty))*C_+c0+tx]=tile[tx][ty];
}

__global__ void pnorm_kernel(const float* __restrict__ xyz){
    int id=blockIdx.x*blockDim.x+threadIdx.x;
    if(id>=B_*N_) return;
    int b=id/N_, n=id%N_;
    const float* Xp=xyz+(size_t)b*3*N_;
    float x=Xp[n], y=Xp[N_+n], z=Xp[2*N_+n];
    g_pnorm[id]=fmaf(z,z,fmaf(x,x,y*y));
}

// pads W_proj and zeroes the BN-stat accumulators (folded stats_zero)
__global__ void wpad_kernel(const float* __restrict__ w){
    int id=blockIdx.x*blockDim.x+threadIdx.x;
    if(id<CO_){ g_sum[id]=0.f; g_sq[id]=0.f; }
    if(id>=CO_*KP0_) return;
    int o=id/KP0_, k=id%KP0_;
    g_Wp[id]=(k<67)?w[o*67+k]:0.0f;
}

__global__ void __launch_bounds__(512,1) fps_kernel(const float* __restrict__ xyz,
                                                    float* __restrict__ out0){
    extern __shared__ u64 fsmu[];
    const int b=blockIdx.x, t=threadIdx.x;
    const float* Xp=xyz+(size_t)b*3*N_;
    u64* sxu=fsmu;
    u64* syu=fsmu+8192;
    u64* szu=fsmu+16384;
    __shared__ int s_bmax[2];
    __shared__ int s_win[2];

    u64 rx[8], ry[8], rz[8];
    float dmin[32];
#pragma unroll
    for(int j=0;j<16;j++){
        int n=j*512+t;
        float x0=Xp[n],        x1=Xp[n+8192];
        float y0=Xp[N_+n],     y1=Xp[N_+n+8192];
        float z0=Xp[2*N_+n],   z1=Xp[2*N_+n+8192];
        u64 px,py,pz;
        PACK_F32X2(px,x0,x1); PACK_F32X2(py,y0,y1); PACK_F32X2(pz,z0,z1);
        sxu[n]=px; syu[n]=py; szu[n]=pz;
        if(j<8){ rx[j]=px; ry[j]=py; rz[j]=pz; }
        dmin[2*j]=1e10f; dmin[2*j+1]=1e10f;
    }
    float cx=Xp[0], cy=Xp[N_], cz=Xp[2*N_];
    if(t==0){
        out0[(size_t)b*3*S_+0]      =cx;
        out0[(size_t)b*3*S_+S_+0]   =cy;
        out0[(size_t)b*3*S_+2*S_+0] =cz;
        float* nz=g_newxyz+(size_t)b*S_*3;
        nz[0]=cx; nz[1]=cy; nz[2]=cz;
        s_bmax[0]=0; s_bmax[1]=0;
        s_win[0]=0x7fffffff; s_win[1]=0x7fffffff;
    }
    __syncthreads();

    const int lane=t&31;
    int p=0;
    for(int it=0; it<S_-1; ++it){
        float ncx=-cx, ncy=-cy, ncz=-cz;
        u64 ncx2,ncy2,ncz2;
        PACK_F32X2(ncx2,ncx,ncx); PACK_F32X2(ncy2,ncy,ncy); PACK_F32X2(ncz2,ncz,ncz);
        float bv=0.0f;
#pragma unroll
        for(int j=0;j<8;j++){
            u64 dx,dy,dz,tt,dd;
            ADD_F32X2(dx,rx[j],ncx2);
            ADD_F32X2(dy,ry[j],ncy2);
            ADD_F32X2(dz,rz[j],ncz2);
            MUL_F32X2(tt,dy,dy);
            FMA_F32X2(tt,dx,dx,tt);
            FMA_F32X2(dd,dz,dz,tt);
            float d0,d1; UNPACK_F32X2(d0,d1,dd);
            float m0=fminf(dmin[2*j],d0);   dmin[2*j]=m0;
            float m1=fminf(dmin[2*j+1],d1); dmin[2*j+1]=m1;
            bv=fmaxf(bv,m0); bv=fmaxf(bv,m1);
        }
#pragma unroll
        for(int j=8;j<16;j++){
            int n=j*512+t;
            u64 dx,dy,dz,tt,dd;
            ADD_F32X2(dx,sxu[n],ncx2);
            ADD_F32X2(dy,syu[n],ncy2);
            ADD_F32X2(dz,szu[n],ncz2);
            MUL_F32X2(tt,dy,dy);
            FMA_F32X2(tt,dx,dx,tt);
            FMA_F32X2(dd,dz,dz,tt);
            float d0,d1; UNPACK_F32X2(d0,d1,dd);
            float m0=fminf(dmin[2*j],d0);   dmin[2*j]=m0;
            float m1=fminf(dmin[2*j+1],d1); dmin[2*j+1]=m1;
            bv=fmaxf(bv,m0); bv=fmaxf(bv,m1);
        }
#pragma unroll
        for(int off=16; off>0; off>>=1)
            bv=fmaxf(bv,__shfl_xor_sync(0xffffffffu,bv,off));
        if(lane==0) atomicMax(&s_bmax[p], __float_as_int(bv));
        __syncthreads();
        const float bmax=__int_as_float(s_bmax[p]);
        if(bv==bmax){
            int cand=0x7fffffff;
#pragma unroll
            for(int k=0;k<32;k++){
                int idx=(k>>1)*512+t+((k&1)<<13);
                if(dmin[k]==bmax) cand=min(cand,idx);
            }
#pragma unroll
            for(int off=16; off>0; off>>=1)
                cand=min(cand,__shfl_xor_sync(0xffffffffu,cand,off));
            if(lane==0) atomicMin(&s_win[p],cand);
        }
        __syncthreads();
        const int w=s_win[p];
        int n=w&8191, hi=w>>13;
        float a0,a1;
        UNPACK_F32X2(a0,a1,sxu[n]); cx = hi? a1:a0;
        UNPACK_F32X2(a0,a1,syu[n]); cy = hi? a1:a0;
        UNPACK_F32X2(a0,a1,szu[n]); cz = hi? a1:a0;
        if(t==0){ s_bmax[p^1]=0; s_win[p^1]=0x7fffffff; }
        if(t==32){
            out0[(size_t)b*3*S_+(it+1)]       =cx;
            out0[(size_t)b*3*S_+S_+(it+1)]    =cy;
            out0[(size_t)b*3*S_+2*S_+(it+1)]  =cz;
            float* nz=g_newxyz+((size_t)b*S_+(it+1))*3;
            nz[0]=cx; nz[1]=cy; nz[2]=cz;
        }
        p^=1;
    }
}

__global__ void query_kernel(const float* __restrict__ xyz){
    int gw=(blockIdx.x*blockDim.x+threadIdx.x)>>5;
    int lane=threadIdx.x&31;
    if(gw>=B_*S_) return;
    int b=gw/S_;
    const float* nz=g_newxyz+(size_t)gw*3;
    float cx=nz[0],cy=nz[1],cz=nz[2];
    float srcn=fmaf(cz,cz,fmaf(cx,cx,cy*cy));
    const float* Xp=xyz+(size_t)b*3*N_;
    const float* pn=g_pnorm+(size_t)b*N_;
    int* dst=g_idx+(size_t)gw*K_;
    int count=0, first=0; bool haveFirst=false;
    for(int base=0; base<N_; base+=32){
        int n=base+lane;
        float dot=fmaf(cz,Xp[2*N_+n],fmaf(cy,Xp[N_+n],cx*Xp[n]));
        float d=fmaf(-2.0f,dot,srcn)+pn[n];
        bool ok=!(d>0.04f);
        unsigned m=__ballot_sync(0xffffffffu,ok);
        if(m){
            if(!haveFirst){first=base+__ffs(m)-1; haveFirst=true;}
            int rank=__popc(m&((1u<<lane)-1u));
            if(ok&&(count+rank)<K_) dst[count+rank]=n;
            count+=__popc(m);
            if(count>=K_) break;
        }
    }
    if(count<K_){
        for(int sl=count+lane; sl<K_; sl+=32) dst[sl]=first;
    }
}

// MODE: 0=raw A, 1=bn+relu on A, 2=gather-build A (proj),
//       3=A = relu(bnA(a) + relu(bnB(a0)))   — scalar FFMA microkernel (R9)
template<int K, int MODE>
__global__ void __launch_bounds__(256,2) gemm_kernel(const float* __restrict__ A,
                                                     const float* __restrict__ W,
                                                     float* __restrict__ Y,
                                                     const float* __restrict__ xyz,
                                                     const float* __restrict__ scA,
                                                     const float* __restrict__ shA,
                                                     const float* __restrict__ A0,
                                                     const float* __restrict__ scB,
                                                     const float* __restrict__ shB){
    __shared__ float As[2][8][128];
    __shared__ float Bs[2][8][128];
    const int tid=threadIdx.x, m0=blockIdx.x<<7;
    const int tm=tid>>4, tn=tid&15;
    const int lrow=tid>>1, lcol=(tid&1)<<2;
    const int row=m0+lrow;

    const float* gsrc=nullptr; const float* xp=nullptr;
    float ncx=0.f,ncy=0.f,ncz=0.f; int jj=0;
    if(MODE==2){
        jj=g_idx[row];
        int bidx=row>>16;
        int cent=row>>5;
        ncx=g_newxyz[cent*3+0]; ncy=g_newxyz[cent*3+1]; ncz=g_newxyz[cent*3+2];
        gsrc=g_ptsT+((size_t)bidx*N_+jj)*C_;
        xp=xyz+(size_t)bidx*3*N_;
    }
    const float* Aptr=A+(size_t)row*K+lcol;
    const float* A0ptr=(MODE==3)? A0+(size_t)row*K+lcol : nullptr;
    const float* Wptr=W+(size_t)lrow*K+lcol;

    auto loadA=[&](int k0)->float4{
        if(MODE==2){
            float v[4];
#pragma unroll
            for(int q=0;q<4;q++){
                int c=k0+lcol+q;
                float t;
                if(c<3){ float nn=(c==0)?ncx:((c==1)?ncy:ncz); t=xp[(size_t)c*N_+jj]-nn; }
                else if(c<67) t=gsrc[c-3];
                else t=0.f;
                v[q]=t;
            }
            return make_float4(v[0],v[1],v[2],v[3]);
        }else{
            float4 a=*reinterpret_cast<const float4*>(Aptr+k0);
            if(MODE==1){
                int c=k0+lcol;
                float4 sc=*reinterpret_cast<const float4*>(&scA[c]);
                float4 sh=*reinterpret_cast<const float4*>(&shA[c]);
                a.x=fmaxf(0.f,fmaf(a.x,sc.x,sh.x));
                a.y=fmaxf(0.f,fmaf(a.y,sc.y,sh.y));
                a.z=fmaxf(0.f,fmaf(a.z,sc.z,sh.z));
                a.w=fmaxf(0.f,fmaf(a.w,sc.w,sh.w));
            }else if(MODE==3){
                int c=k0+lcol;
                float4 a0=*reinterpret_cast<const float4*>(A0ptr+k0);
                float4 sc=*reinterpret_cast<const float4*>(&scA[c]);
                float4 sh=*reinterpret_cast<const float4*>(&shA[c]);
                float4 s0=*reinterpret_cast<const float4*>(&scB[c]);
                float4 h0=*reinterpret_cast<const float4*>(&shB[c]);
                float x0=fmaxf(0.f,fmaf(a0.x,s0.x,h0.x));
                float x1=fmaxf(0.f,fmaf(a0.y,s0.y,h0.y));
                float x2=fmaxf(0.f,fmaf(a0.z,s0.z,h0.z));
                float x3=fmaxf(0.f,fmaf(a0.w,s0.w,h0.w));
                a.x=fmaxf(0.f,fmaf(a.x,sc.x,sh.x)+x0);
                a.y=fmaxf(0.f,fmaf(a.y,sc.y,sh.y)+x1);
                a.z=fmaxf(0.f,fmaf(a.z,sc.z,sh.z)+x2);
                a.w=fmaxf(0.f,fmaf(a.w,sc.w,sh.w)+x3);
            }
            return a;
        }
    };

    float acc[8][8];
#pragma unroll
    for(int i=0;i<8;i++)
#pragma unroll
        for(int j=0;j<8;j++) acc[i][j]=0.0f;

    constexpr int NT=K/8;
    float4 av=loadA(0);
    float4 wv=*reinterpret_cast<const float4*>(Wptr);
    As[0][lcol+0][lrow]=av.x; As[0][lcol+1][lrow]=av.y; As[0][lcol+2][lrow]=av.z; As[0][lcol+3][lrow]=av.w;
    Bs[0][lcol+0][lrow]=wv.x; Bs[0][lcol+1][lrow]=wv.y; Bs[0][lcol+2][lrow]=wv.z; Bs[0][lcol+3][lrow]=wv.w;
    __syncthreads();

    for(int it=0; it<NT; ++it){
        const int cur=it&1;
        if(it+1<NT){
            av=loadA((it+1)*8);
            wv=*reinterpret_cast<const float4*>(Wptr+(it+1)*8);
        }
#pragma unroll
        for(int kk=0;kk<8;kk++){
            float4 a0=*reinterpret_cast<const float4*>(&As[cur][kk][tm<<3]);
            float4 a1=*reinterpret_cast<const float4*>(&As[cur][kk][(tm<<3)+4]);
            float4 b0=*reinterpret_cast<const float4*>(&Bs[cur][kk][tn<<3]);
            float4 b1=*reinterpret_cast<const float4*>(&Bs[cur][kk][(tn<<3)+4]);
            float a[8]={a0.x,a0.y,a0.z,a0.w,a1.x,a1.y,a1.z,a1.w};
            float w8[8]={b0.x,b0.y,b0.z,b0.w,b1.x,b1.y,b1.z,b1.w};
#pragma unroll
            for(int i=0;i<8;i++)
#pragma unroll
                for(int j=0;j<8;j++) acc[i][j]=fmaf(a[i],w8[j],acc[i][j]);
        }
        if(it+1<NT){
            const int nxt=cur^1;
            As[nxt][lcol+0][lrow]=av.x; As[nxt][lcol+1][lrow]=av.y; As[nxt][lcol+2][lrow]=av.z; As[nxt][lcol+3][lrow]=av.w;
            Bs[nxt][lcol+0][lrow]=wv.x; Bs[nxt][lcol+1][lrow]=wv.y; Bs[nxt][lcol+2][lrow]=wv.z; Bs[nxt][lcol+3][lrow]=wv.w;
        }
        __syncthreads();
    }

#pragma unroll
    for(int i=0;i<8;i++){
        float* yp=Y+(size_t)(m0+(tm<<3)+i)*CO_+(tn<<3);
        *reinterpret_cast<float4*>(yp)  =make_float4(acc[i][0],acc[i][1],acc[i][2],acc[i][3]);
        *reinterpret_cast<float4*>(yp+4)=make_float4(acc[i][4],acc[i][5],acc[i][6],acc[i][7]);
    }

    float cs[8], cq[8];
#pragma unroll
    for(int j=0;j<8;j++){
        float s=0.f,q=0.f;
#pragma unroll
        for(int i=0;i<8;i++){ float v=acc[i][j]; s+=v; q=fmaf(v,v,q); }
        cs[j]=s; cq[j]=q;
    }
    float* ss=&As[0][0][0];
#pragma unroll
    for(int j=0;j<8;j++) ss[tm*128 + (tn<<3)+j]=cs[j];
    __syncthreads();
    if(tid<128){
        float s=0.f;
#pragma unroll
        for(int t=0;t<16;t++) s+=ss[t*128+tid];
        atomicAdd(&g_sum[tid], s);
    }
    __syncthreads();
#pragma unroll
    for(int j=0;j<8;j++) ss[tm*128 + (tn<<3)+j]=cq[j];
    __syncthreads();
    if(tid<128){
        float s=0.f;
#pragma unroll
        for(int t=0;t<16;t++) s+=ss[t*128+tid];
        atomicAdd(&g_sq[tid], s);
    }
}

__global__ void finalize_kernel(const float* __restrict__ gg, const float* __restrict__ bb,
                                float* __restrict__ sc_out, float* __restrict__ sh_out){
    int c=threadIdx.x;
    if(c<CO_){
        const float inv=1.0f/(float)M_;
        float mu=g_sum[c]*inv;
        float var=g_sq[c]*inv-mu*mu;
        float rs=rsqrtf(var+1e-5f);
        float sc=gg[c]*rs;
        sc_out[c]=sc;
        sh_out[c]=bb[c]-mu*sc;
        g_sum[c]=0.f; g_sq[c]=0.f;
    }
}

__global__ void maxpool3_kernel(const float* __restrict__ Y4, const float* __restrict__ Y2,
                                const float* __restrict__ Y0, float* __restrict__ out2,
                                const float* __restrict__ scL, const float* __restrict__ shL){
    int id=blockIdx.x*blockDim.x+threadIdx.x;
    int c=id&127;
    int s=(id>>7)&(S_-1);
    int b=id>>18;
    size_t base=((size_t)(b*S_+s)*K_)*CO_+c;
    float sc0=scL[0*CO_+c], sh0=shL[0*CO_+c];
    float sc2=scL[2*CO_+c], sh2=shL[2*CO_+c];
    float sc4=scL[4*CO_+c], sh4=shL[4*CO_+c];
    float m=-1e30f;
#pragma unroll
    for(int k=0;k<K_;k++){
        size_t o=base+(size_t)k*CO_;
        float x0=fmaxf(0.f,fmaf(Y0[o],sc0,sh0));
        float xr=fmaxf(0.f,fmaf(Y2[o],sc2,sh2)+x0);
        float v =fmaxf(0.f,fmaf(Y4[o],sc4,sh4)+xr);
        m=fmaxf(m,v);
    }
    out2[((size_t)b*CO_+c)*S_+s]=m;
}

extern "C" void kernel_launch(void* const* d_in, const int* in_sizes, int n_in,
                              void* d_out, int out_size){
    const float* xyz  =(const float*)d_in[0];
    const float* pts  =(const float*)d_in[1];
    const float* wproj=(const float*)d_in[2];
    const float* gproj=(const float*)d_in[3];
    const float* bproj=(const float*)d_in[4];
    const float* w1   =(const float*)d_in[5];
    const float* w2   =(const float*)d_in[6];
    const float* g1   =(const float*)d_in[7];
    const float* b1   =(const float*)d_in[8];
    const float* g2   =(const float*)d_in[9];
    const float* b2   =(const float*)d_in[10];
    float* out=(float*)d_out;

    void *pYv,*pXv,*pHv,*pZv,*pWpv,*pScv,*pShv;
    cudaGetSymbolAddress(&pYv, g_Ybuf);
    cudaGetSymbolAddress(&pXv, g_Xbuf);
    cudaGetSymbolAddress(&pHv, g_Hbuf);
    cudaGetSymbolAddress(&pZv, g_Zbuf);
    cudaGetSymbolAddress(&pWpv,g_Wp);
    cudaGetSymbolAddress(&pScv,g_scaleL);
    cudaGetSymbolAddress(&pShv,g_shiftL);
    float* pY=(float*)pYv; float* pX=(float*)pXv; float* pH=(float*)pHv;
    float* pZ=(float*)pZv; float* pWp=(float*)pWpv;
    float* scL=(float*)pScv; float* shL=(float*)pShv;

    cudaFuncSetAttribute(fps_kernel, cudaFuncAttributeMaxDynamicSharedMemorySize, 3*8192*8);

    transpose_pts<<<dim3(N_/32, C_/32, B_), dim3(32,32)>>>(pts);
    pnorm_kernel<<<(B_*N_+1023)/1024,1024>>>(xyz);
    wpad_kernel<<<(CO_*KP0_+1023)/1024,1024>>>(wproj);

    fps_kernel<<<B_,512,3*8192*8>>>(xyz,out);
    query_kernel<<<(B_*S_*32)/256,256>>>(xyz);

    const int GG=M_/128;

    gemm_kernel<KP0_,2><<<GG,256>>>(pY, pWp, pY, xyz, scL, shL, nullptr, nullptr, nullptr);
    finalize_kernel<<<1,128>>>(gproj, bproj, scL+0*CO_, shL+0*CO_);

    gemm_kernel<128,1><<<GG,256>>>(pY, w1, pH, xyz, scL+0*CO_, shL+0*CO_, nullptr, nullptr, nullptr);
    finalize_kernel<<<1,128>>>(g1, b1, scL+1*CO_, shL+1*CO_);
    gemm_kernel<128,1><<<GG,256>>>(pH, w2, pX, xyz, scL+1*CO_, shL+1*CO_, nullptr, nullptr, nullptr);
    finalize_kernel<<<1,128>>>(g2, b2, scL+2*CO_, shL+2*CO_);

    gemm_kernel<128,3><<<GG,256>>>(pX, w1+CO_*CO_, pZ, xyz,
                                   scL+2*CO_, shL+2*CO_, pY, scL+0*CO_, shL+0*CO_);
    finalize_kernel<<<1,128>>>(g1+CO_, b1+CO_, scL+3*CO_, shL+3*CO_);
    gemm_kernel<128,1><<<GG,256>>>(pZ, w2+CO_*CO_, pH, xyz, scL+3*CO_, shL+3*CO_, nullptr, nullptr, nullptr);
    finalize_kernel<<<1,128>>>(g2+CO_, b2+CO_, scL+4*CO_, shL+4*CO_);

    maxpool3_kernel<<<(B_*S_*CO_)/256,256>>>(pH, pX, pY, out + B_*3*S_, scL, shL);
}

// round 12
// speedup vs baseline: 1.4921x; 1.0670x over previous
#include <cuda_runtime.h>
#include <cstdint>

#define B_   4
#define N_   16384
#define C_   64
#define S_   2048
#define K_   32
#define M_   (B_*S_*K_)
#define CO_  128
#define KP0_ 72

#define PACK_F32X2(out, lo, hi) \
    asm("mov.b64 %0, {%1, %2};" : "=l"(out) : "f"(lo), "f"(hi))
#define UNPACK_F32X2(lo, hi, in) \
    asm("mov.b64 {%0, %1}, %2;" : "=f"(lo), "=f"(hi) : "l"(in))
#define ADD_F32X2(out, a, b) \
    asm("add.rn.f32x2 %0, %1, %2;" : "=l"(out) : "l"(a), "l"(b))
#define MUL_F32X2(out, a, b) \
    asm("mul.rn.f32x2 %0, %1, %2;" : "=l"(out) : "l"(a), "l"(b))
#define FMA_F32X2(out, a, b, c) \
    asm("fma.rn.f32x2 %0, %1, %2, %3;" : "=l"(out) : "l"(a), "l"(b), "l"(c))

typedef unsigned long long u64;
typedef unsigned int u32;

__device__ __align__(16) float g_newxyz[B_*S_*3];
__device__ int   g_idx[B_*S_*K_];
__device__ __align__(16) float g_ptsT[(size_t)B_*N_*C_];
__device__ float g_pnorm[B_*N_];
__device__ __align__(16) float g_Ybuf[(size_t)M_*CO_];
__device__ __align__(16) float g_Xbuf[(size_t)M_*CO_];
__device__ __align__(16) float g_Hbuf[(size_t)M_*CO_];
__device__ __align__(16) float g_Zbuf[(size_t)M_*CO_];
__device__ __align__(16) float g_Wp[CO_*KP0_];
__device__ __align__(16) float g_sum[CO_];
__device__ __align__(16) float g_sq[CO_];
__device__ __align__(16) float g_scaleL[5*CO_];
__device__ __align__(16) float g_shiftL[5*CO_];

__device__ __forceinline__ float tf32_hi(float a){
    u32 u; asm("cvt.rna.tf32.f32 %0, %1;" : "=r"(u) : "f"(a));
    return __uint_as_float(u);
}
__device__ __forceinline__ void mma_tf32(float* d, u32 a0,u32 a1,u32 a2,u32 a3, u32 b0,u32 b1){
    asm("mma.sync.aligned.m16n8k8.row.col.f32.tf32.tf32.f32 "
        "{%0,%1,%2,%3},{%4,%5,%6,%7},{%8,%9},{%0,%1,%2,%3};"
        : "+f"(d[0]),"+f"(d[1]),"+f"(d[2]),"+f"(d[3])
        : "r"(a0),"r"(a1),"r"(a2),"r"(a3),"r"(b0),"r"(b1));
}

__global__ void transpose_pts(const float* __restrict__ pts){
    __shared__ float tile[32][33];
    int b=blockIdx.z, n0=blockIdx.x<<5, c0=blockIdx.y<<5;
    int tx=threadIdx.x, ty=threadIdx.y;
    tile[ty][tx]=pts[((size_t)b*C_+(c0+ty))*N_+n0+tx];
    __syncthreads();
    g_ptsT[((size_t)b*N_+(n0+ty))*C_+c0+tx]=tile[tx][ty];
}

__global__ void pnorm_kernel(const float* __restrict__ xyz){
    int id=blockIdx.x*blockDim.x+threadIdx.x;
    if(id>=B_*N_) return;
    int b=id/N_, n=id%N_;
    const float* Xp=xyz+(size_t)b*3*N_;
    float x=Xp[n], y=Xp[N_+n], z=Xp[2*N_+n];
    g_pnorm[id]=fmaf(z,z,fmaf(x,x,y*y));
}

__global__ void wpad_kernel(const float* __restrict__ w){
    int id=blockIdx.x*blockDim.x+threadIdx.x;
    if(id<CO_){ g_sum[id]=0.f; g_sq[id]=0.f; }
    if(id>=CO_*KP0_) return;
    int o=id/KP0_, k=id%KP0_;
    g_Wp[id]=(k<67)?w[o*67+k]:0.0f;
}

__global__ void __launch_bounds__(512,1) fps_kernel(const float* __restrict__ xyz,
                                                    float* __restrict__ out0){
    extern __shared__ u64 fsmu[];
    const int b=blockIdx.x, t=threadIdx.x;
    const float* Xp=xyz+(size_t)b*3*N_;
    u64* sxu=fsmu;
    u64* syu=fsmu+8192;
    u64* szu=fsmu+16384;
    __shared__ int s_bmax[2];
    __shared__ int s_win[2];

    u64 rx[8], ry[8], rz[8];
    float dmin[32];
#pragma unroll
    for(int j=0;j<16;j++){
        int n=j*512+t;
        float x0=Xp[n],        x1=Xp[n+8192];
        float y0=Xp[N_+n],     y1=Xp[N_+n+8192];
        float z0=Xp[2*N_+n],   z1=Xp[2*N_+n+8192];
        u64 px,py,pz;
        PACK_F32X2(px,x0,x1); PACK_F32X2(py,y0,y1); PACK_F32X2(pz,z0,z1);
        sxu[n]=px; syu[n]=py; szu[n]=pz;
        if(j<8){ rx[j]=px; ry[j]=py; rz[j]=pz; }
        dmin[2*j]=1e10f; dmin[2*j+1]=1e10f;
    }
    float cx=Xp[0], cy=Xp[N_], cz=Xp[2*N_];
    if(t==0){
        out0[(size_t)b*3*S_+0]      =cx;
        out0[(size_t)b*3*S_+S_+0]   =cy;
        out0[(size_t)b*3*S_+2*S_+0] =cz;
        float* nz=g_newxyz+(size_t)b*S_*3;
        nz[0]=cx; nz[1]=cy; nz[2]=cz;
        s_bmax[0]=0; s_bmax[1]=0;
        s_win[0]=0x7fffffff; s_win[1]=0x7fffffff;
    }
    __syncthreads();

    const int lane=t&31;
    int p=0;
    for(int it=0; it<S_-1; ++it){
        float ncx=-cx, ncy=-cy, ncz=-cz;
        u64 ncx2,ncy2,ncz2;
        PACK_F32X2(ncx2,ncx,ncx); PACK_F32X2(ncy2,ncy,ncy); PACK_F32X2(ncz2,ncz,ncz);
        float bv=0.0f;
#pragma unroll
        for(int j=0;j<8;j++){
            u64 dx,dy,dz,tt,dd;
            ADD_F32X2(dx,rx[j],ncx2);
            ADD_F32X2(dy,ry[j],ncy2);
            ADD_F32X2(dz,rz[j],ncz2);
            MUL_F32X2(tt,dy,dy);
            FMA_F32X2(tt,dx,dx,tt);
            FMA_F32X2(dd,dz,dz,tt);
            float d0,d1; UNPACK_F32X2(d0,d1,dd);
            float m0=fminf(dmin[2*j],d0);   dmin[2*j]=m0;
            float m1=fminf(dmin[2*j+1],d1); dmin[2*j+1]=m1;
            bv=fmaxf(bv,m0); bv=fmaxf(bv,m1);
        }
#pragma unroll
        for(int j=8;j<16;j++){
            int n=j*512+t;
            u64 dx,dy,dz,tt,dd;
            ADD_F32X2(dx,sxu[n],ncx2);
            ADD_F32X2(dy,syu[n],ncy2);
            ADD_F32X2(dz,szu[n],ncz2);
            MUL_F32X2(tt,dy,dy);
            FMA_F32X2(tt,dx,dx,tt);
            FMA_F32X2(dd,dz,dz,tt);
            float d0,d1; UNPACK_F32X2(d0,d1,dd);
            float m0=fminf(dmin[2*j],d0);   dmin[2*j]=m0;
            float m1=fminf(dmin[2*j+1],d1); dmin[2*j+1]=m1;
            bv=fmaxf(bv,m0); bv=fmaxf(bv,m1);
        }
#pragma unroll
        for(int off=16; off>0; off>>=1)
            bv=fmaxf(bv,__shfl_xor_sync(0xffffffffu,bv,off));
        if(lane==0) atomicMax(&s_bmax[p], __float_as_int(bv));
        __syncthreads();
        const float bmax=__int_as_float(s_bmax[p]);
        if(bv==bmax){
            int cand=0x7fffffff;
#pragma unroll
            for(int k=0;k<32;k++){
                int idx=(k>>1)*512+t+((k&1)<<13);
                if(dmin[k]==bmax) cand=min(cand,idx);
            }
#pragma unroll
            for(int off=16; off>0; off>>=1)
                cand=min(cand,__shfl_xor_sync(0xffffffffu,cand,off));
            if(lane==0) atomicMin(&s_win[p],cand);
        }
        __syncthreads();
        const int w=s_win[p];
        int n=w&8191, hi=w>>13;
        float a0,a1;
        UNPACK_F32X2(a0,a1,sxu[n]); cx = hi? a1:a0;
        UNPACK_F32X2(a0,a1,syu[n]); cy = hi? a1:a0;
        UNPACK_F32X2(a0,a1,szu[n]); cz = hi? a1:a0;
        if(t==0){ s_bmax[p^1]=0; s_win[p^1]=0x7fffffff; }
        if(t==32){
            out0[(size_t)b*3*S_+(it+1)]       =cx;
            out0[(size_t)b*3*S_+S_+(it+1)]    =cy;
            out0[(size_t)b*3*S_+2*S_+(it+1)]  =cz;
            float* nz=g_newxyz+((size_t)b*S_+(it+1))*3;
            nz[0]=cx; nz[1]=cy; nz[2]=cz;
        }
        p^=1;
    }
}

__global__ void query_kernel(const float* __restrict__ xyz){
    int gw=(blockIdx.x*blockDim.x+threadIdx.x)>>5;
    int lane=threadIdx.x&31;
    if(gw>=B_*S_) return;
    int b=gw/S_;
    const float* nz=g_newxyz+(size_t)gw*3;
    float cx=nz[0],cy=nz[1],cz=nz[2];
    float srcn=fmaf(cz,cz,fmaf(cx,cx,cy*cy));
    const float* Xp=xyz+(size_t)b*3*N_;
    const float* pn=g_pnorm+(size_t)b*N_;
    int* dst=g_idx+(size_t)gw*K_;
    int count=0, first=0; bool haveFirst=false;
    for(int base=0; base<N_; base+=32){
        int n=base+lane;
        float dot=fmaf(cz,Xp[2*N_+n],fmaf(cy,Xp[N_+n],cx*Xp[n]));
        float d=fmaf(-2.0f,dot,srcn)+pn[n];
        bool ok=!(d>0.04f);
        unsigned m=__ballot_sync(0xffffffffu,ok);
        if(m){
            if(!haveFirst){first=base+__ffs(m)-1; haveFirst=true;}
            int rank=__popc(m&((1u<<lane)-1u));
            if(ok&&(count+rank)<K_) dst[count+rank]=n;
            count+=__popc(m);
            if(count>=K_) break;
        }
    }
    if(count<K_){
        for(int sl=count+lane; sl<K_; sl+=32) dst[sl]=first;
    }
}

// 3xTF32 tensor-core GEMM. MODE: 0=raw A, 1=bn+relu on A, 2=gather-build A,
// 3=A = relu(bnA(a)+relu(bnB(a0))). Y[M,128] = A[M,K] * W[128,K]^T, fused BN stats.
#define BKP 136
template<int K, int MODE>
__global__ void __launch_bounds__(256,2) gemm_kernel(const float* __restrict__ A,
                                                     const float* __restrict__ W,
                                                     float* __restrict__ Y,
                                                     const float* __restrict__ xyz,
                                                     const float* __restrict__ scA,
                                                     const float* __restrict__ shA,
                                                     const float* __restrict__ A0,
                                                     const float* __restrict__ scB,
                                                     const float* __restrict__ shB){
    __shared__ float Ahi[2][8][BKP];
    __shared__ float Alo[2][8][BKP];
    __shared__ float Bhi[2][8][BKP];
    __shared__ float Blo[2][8][BKP];
    __shared__ float sred[256];
    const int tid=threadIdx.x, m0=blockIdx.x<<7;
    const int lrow=tid>>1, lcol=(tid&1)<<2;
    const int row=m0+lrow;
    const int wid=tid>>5, lane=tid&31;
    const int wm=(wid&3)<<5, wn=(wid>>2)<<6;
    const int g=lane>>2, tg=lane&3;

    if(tid<256) sred[tid]=0.f;

    const float* gsrc=nullptr; const float* xp=nullptr;
    float ncx=0.f,ncy=0.f,ncz=0.f; int jj=0;
    if(MODE==2){
        jj=g_idx[row];
        int bidx=row>>16;
        int cent=row>>5;
        ncx=g_newxyz[cent*3+0]; ncy=g_newxyz[cent*3+1]; ncz=g_newxyz[cent*3+2];
        gsrc=g_ptsT+((size_t)bidx*N_+jj)*C_;
        xp=xyz+(size_t)bidx*3*N_;
    }
    const float* Aptr=A+(size_t)row*K+lcol;
    const float* A0ptr=(MODE==3)? A0+(size_t)row*K+lcol : nullptr;
    const float* Wptr=W+(size_t)lrow*K+lcol;

    auto loadA=[&](int k0)->float4{
        if(MODE==2){
            float v[4];
#pragma unroll
            for(int q=0;q<4;q++){
                int c=k0+lcol+q;
                float t;
                if(c<3){ float nn=(c==0)?ncx:((c==1)?ncy:ncz); t=xp[(size_t)c*N_+jj]-nn; }
                else if(c<67) t=gsrc[c-3];
                else t=0.f;
                v[q]=t;
            }
            return make_float4(v[0],v[1],v[2],v[3]);
        }else{
            float4 a=*reinterpret_cast<const float4*>(Aptr+k0);
            if(MODE==1){
                int c=k0+lcol;
                float4 sc=*reinterpret_cast<const float4*>(&scA[c]);
                float4 sh=*reinterpret_cast<const float4*>(&shA[c]);
                a.x=fmaxf(0.f,fmaf(a.x,sc.x,sh.x));
                a.y=fmaxf(0.f,fmaf(a.y,sc.y,sh.y));
                a.z=fmaxf(0.f,fmaf(a.z,sc.z,sh.z));
                a.w=fmaxf(0.f,fmaf(a.w,sc.w,sh.w));
            }else if(MODE==3){
                int c=k0+lcol;
                float4 a0=*reinterpret_cast<const float4*>(A0ptr+k0);
                float4 sc=*reinterpret_cast<const float4*>(&scA[c]);
                float4 sh=*reinterpret_cast<const float4*>(&shA[c]);
                float4 s0=*reinterpret_cast<const float4*>(&scB[c]);
                float4 h0=*reinterpret_cast<const float4*>(&shB[c]);
                float x0=fmaxf(0.f,fmaf(a0.x,s0.x,h0.x));
                float x1=fmaxf(0.f,fmaf(a0.y,s0.y,h0.y));
                float x2=fmaxf(0.f,fmaf(a0.z,s0.z,h0.z));
                float x3=fmaxf(0.f,fmaf(a0.w,s0.w,h0.w));
                a.x=fmaxf(0.f,fmaf(a.x,sc.x,sh.x)+x0);
                a.y=fmaxf(0.f,fmaf(a.y,sc.y,sh.y)+x1);
                a.z=fmaxf(0.f,fmaf(a.z,sc.z,sh.z)+x2);
                a.w=fmaxf(0.f,fmaf(a.w,sc.w,sh.w)+x3);
            }
            return a;
        }
    };

    auto stage=[&](int buf, float4 av, float4 wv){
        float af[4]={av.x,av.y,av.z,av.w};
        float wf[4]={wv.x,wv.y,wv.z,wv.w};
#pragma unroll
        for(int q=0;q<4;q++){
            float ah=tf32_hi(af[q]);
            Ahi[buf][lcol+q][lrow]=ah;
            Alo[buf][lcol+q][lrow]=af[q]-ah;
            float wh=tf32_hi(wf[q]);
            Bhi[buf][lcol+q][lrow]=wh;
            Blo[buf][lcol+q][lrow]=wf[q]-wh;
        }
    };

    float d[2][8][4];
#pragma unroll
    for(int mt=0;mt<2;mt++)
#pragma unroll
        for(int nt=0;nt<8;nt++)
#pragma unroll
            for(int q=0;q<4;q++) d[mt][nt][q]=0.f;

    constexpr int NT=K/8;
    float4 av=loadA(0);
    float4 wv=*reinterpret_cast<const float4*>(Wptr);
    stage(0,av,wv);
    __syncthreads();

    for(int it=0; it<NT; ++it){
        const int cur=it&1;
        if(it+1<NT){
            av=loadA((it+1)*8);
            wv=*reinterpret_cast<const float4*>(Wptr+(it+1)*8);
        }
        u32 ah[2][4], al[2][4];
#pragma unroll
        for(int mt=0;mt<2;mt++){
            int r0=wm+(mt<<4)+g;
            ah[mt][0]=__float_as_uint(Ahi[cur][tg  ][r0]);
            ah[mt][1]=__float_as_uint(Ahi[cur][tg  ][r0+8]);
            ah[mt][2]=__float_as_uint(Ahi[cur][tg+4][r0]);
            ah[mt][3]=__float_as_uint(Ahi[cur][tg+4][r0+8]);
            al[mt][0]=__float_as_uint(Alo[cur][tg  ][r0]);
            al[mt][1]=__float_as_uint(Alo[cur][tg  ][r0+8]);
            al[mt][2]=__float_as_uint(Alo[cur][tg+4][r0]);
            al[mt][3]=__float_as_uint(Alo[cur][tg+4][r0+8]);
        }
#pragma unroll
        for(int nt=0;nt<8;nt++){
            int nn=wn+(nt<<3)+g;
            u32 bh0=__float_as_uint(Bhi[cur][tg  ][nn]);
            u32 bh1=__float_as_uint(Bhi[cur][tg+4][nn]);
            u32 bl0=__float_as_uint(Blo[cur][tg  ][nn]);
            u32 bl1=__float_as_uint(Blo[cur][tg+4][nn]);
#pragma unroll
            for(int mt=0;mt<2;mt++){
                mma_tf32(d[mt][nt], ah[mt][0],ah[mt][1],ah[mt][2],ah[mt][3], bh0,bh1);
                mma_tf32(d[mt][nt], ah[mt][0],ah[mt][1],ah[mt][2],ah[mt][3], bl0,bl1);
                mma_tf32(d[mt][nt], al[mt][0],al[mt][1],al[mt][2],al[mt][3], bh0,bh1);
            }
        }
        if(it+1<NT) stage(cur^1,av,wv);
        __syncthreads();
    }

    // epilogue: store Y + fused BN stats
    float cs[8][2], cq[8][2];
#pragma unroll
    for(int nt=0;nt<8;nt++){ cs[nt][0]=0.f; cs[nt][1]=0.f; cq[nt][0]=0.f; cq[nt][1]=0.f; }
#pragma unroll
    for(int nt=0;nt<8;nt++){
        int nbase=wn+(nt<<3)+(tg<<1);
#pragma unroll
        for(int mt=0;mt<2;mt++){
            int mlo=m0+wm+(mt<<4)+g;
            float d0=d[mt][nt][0], d1=d[mt][nt][1], d2=d[mt][nt][2], d3=d[mt][nt][3];
            *reinterpret_cast<float2*>(&Y[(size_t)mlo*CO_+nbase])    =make_float2(d0,d1);
            *reinterpret_cast<float2*>(&Y[(size_t)(mlo+8)*CO_+nbase])=make_float2(d2,d3);
            cs[nt][0]+=d0+d2; cs[nt][1]+=d1+d3;
            cq[nt][0]=fmaf(d0,d0,cq[nt][0]); cq[nt][0]=fmaf(d2,d2,cq[nt][0]);
            cq[nt][1]=fmaf(d1,d1,cq[nt][1]); cq[nt][1]=fmaf(d3,d3,cq[nt][1]);
        }
    }
    // reduce across lanes sharing tg (offsets 4,8,16 preserve tg)
#pragma unroll
    for(int off=4; off<32; off<<=1){
#pragma unroll
        for(int nt=0;nt<8;nt++){
            cs[nt][0]+=__shfl_xor_sync(0xffffffffu,cs[nt][0],off);
            cs[nt][1]+=__shfl_xor_sync(0xffffffffu,cs[nt][1],off);
            cq[nt][0]+=__shfl_xor_sync(0xffffffffu,cq[nt][0],off);
            cq[nt][1]+=__shfl_xor_sync(0xffffffffu,cq[nt][1],off);
        }
    }
    if(lane<4){
#pragma unroll
        for(int nt=0;nt<8;nt++){
            int col=wn+(nt<<3)+(lane<<1);
            atomicAdd(&sred[col],     cs[nt][0]);
            atomicAdd(&sred[col+1],   cs[nt][1]);
            atomicAdd(&sred[128+col],   cq[nt][0]);
            atomicAdd(&sred[128+col+1], cq[nt][1]);
        }
    }
    __syncthreads();
    if(tid<128){
        atomicAdd(&g_sum[tid], sred[tid]);
        atomicAdd(&g_sq[tid],  sred[128+tid]);
    }
}

__global__ void finalize_kernel(const float* __restrict__ gg, const float* __restrict__ bb,
                                float* __restrict__ sc_out, float* __restrict__ sh_out){
    int c=threadIdx.x;
    if(c<CO_){
        const float inv=1.0f/(float)M_;
        float mu=g_sum[c]*inv;
        float var=g_sq[c]*inv-mu*mu;
        float rs=rsqrtf(var+1e-5f);
        float sc=gg[c]*rs;
        sc_out[c]=sc;
        sh_out[c]=bb[c]-mu*sc;
        g_sum[c]=0.f; g_sq[c]=0.f;
    }
}

__global__ void maxpool3_kernel(const float* __restrict__ Y4, const float* __restrict__ Y2,
                                const float* __restrict__ Y0, float* __restrict__ out2,
                                const float* __restrict__ scL, const float* __restrict__ shL){
    int id=blockIdx.x*blockDim.x+threadIdx.x;
    int c=id&127;
    int s=(id>>7)&(S_-1);
    int b=id>>18;
    size_t base=((size_t)(b*S_+s)*K_)*CO_+c;
    float sc0=scL[0*CO_+c], sh0=shL[0*CO_+c];
    float sc2=scL[2*CO_+c], sh2=shL[2*CO_+c];
    float sc4=scL[4*CO_+c], sh4=shL[4*CO_+c];
    float m=-1e30f;
#pragma unroll
    for(int k=0;k<K_;k++){
        size_t o=base+(size_t)k*CO_;
        float x0=fmaxf(0.f,fmaf(Y0[o],sc0,sh0));
        float xr=fmaxf(0.f,fmaf(Y2[o],sc2,sh2)+x0);
        float v =fmaxf(0.f,fmaf(Y4[o],sc4,sh4)+xr);
        m=fmaxf(m,v);
    }
    out2[((size_t)b*CO_+c)*S_+s]=m;
}

extern "C" void kernel_launch(void* const* d_in, const int* in_sizes, int n_in,
                              void* d_out, int out_size){
    const float* xyz  =(const float*)d_in[0];
    const float* pts  =(const float*)d_in[1];
    const float* wproj=(const float*)d_in[2];
    const float* gproj=(const float*)d_in[3];
    const float* bproj=(const float*)d_in[4];
    const float* w1   =(const float*)d_in[5];
    const float* w2   =(const float*)d_in[6];
    const float* g1   =(const float*)d_in[7];
    const float* b1   =(const float*)d_in[8];
    const float* g2   =(const float*)d_in[9];
    const float* b2   =(const float*)d_in[10];
    float* out=(float*)d_out;

    void *pYv,*pXv,*pHv,*pZv,*pWpv,*pScv,*pShv;
    cudaGetSymbolAddress(&pYv, g_Ybuf);
    cudaGetSymbolAddress(&pXv, g_Xbuf);
    cudaGetSymbolAddress(&pHv, g_Hbuf);
    cudaGetSymbolAddress(&pZv, g_Zbuf);
    cudaGetSymbolAddress(&pWpv,g_Wp);
    cudaGetSymbolAddress(&pScv,g_scaleL);
    cudaGetSymbolAddress(&pShv,g_shiftL);
    float* pY=(float*)pYv; float* pX=(float*)pXv; float* pH=(float*)pHv;
    float* pZ=(float*)pZv; float* pWp=(float*)pWpv;
    float* scL=(float*)pScv; float* shL=(float*)pShv;

    cudaFuncSetAttribute(fps_kernel, cudaFuncAttributeMaxDynamicSharedMemorySize, 3*8192*8);

    transpose_pts<<<dim3(N_/32, C_/32, B_), dim3(32,32)>>>(pts);
    pnorm_kernel<<<(B_*N_+1023)/1024,1024>>>(xyz);
    wpad_kernel<<<(CO_*KP0_+1023)/1024,1024>>>(wproj);

    fps_kernel<<<B_,512,3*8192*8>>>(xyz,out);
    query_kernel<<<(B_*S_*32)/256,256>>>(xyz);

    const int GG=M_/128;

    gemm_kernel<KP0_,2><<<GG,256>>>(pY, pWp, pY, xyz, scL, shL, nullptr, nullptr, nullptr);
    finalize_kernel<<<1,128>>>(gproj, bproj, scL+0*CO_, shL+0*CO_);

    gemm_kernel<128,1><<<GG,256>>>(pY, w1, pH, xyz, scL+0*CO_, shL+0*CO_, nullptr, nullptr, nullptr);
    finalize_kernel<<<1,128>>>(g1, b1, scL+1*CO_, shL+1*CO_);
    gemm_kernel<128,1><<<GG,256>>>(pH, w2, pX, xyz, scL+1*CO_, shL+1*CO_, nullptr, nullptr, nullptr);
    finalize_kernel<<<1,128>>>(g2, b2, scL+2*CO_, shL+2*CO_);

    gemm_kernel<128,3><<<GG,256>>>(pX, w1+CO_*CO_, pZ, xyz,
                                   scL+2*CO_, shL+2*CO_, pY, scL+0*CO_, shL+0*CO_);
    finalize_kernel<<<1,128>>>(g1+CO_, b1+CO_, scL+3*CO_, shL+3*CO_);
    gemm_kernel<128,1><<<GG,256>>>(pZ, w2+CO_*CO_, pH, xyz, scL+3*CO_, shL+3*CO_, nullptr, nullptr, nullptr);
    finalize_kernel<<<1,128>>>(g2+CO_, b2+CO_, scL+4*CO_, shL+4*CO_);

    maxpool3_kernel<<<(B_*S_*CO_)/256,256>>>(pH, pX, pY, out + B_*3*S_, scL, shL);
}

// round 13
// speedup vs baseline: 1.6036x; 1.0747x over previous
#include <cuda_runtime.h>
#include <cuda_bf16.h>
#include <cstdint>

#define B_   4
#define N_   16384
#define C_   64
#define S_   2048
#define K_   32
#define M_   (B_*S_*K_)
#define CO_  128
#define KP0_ 80

#define PACK_F32X2(out, lo, hi) \
    asm("mov.b64 %0, {%1, %2};" : "=l"(out) : "f"(lo), "f"(hi))
#define UNPACK_F32X2(lo, hi, in) \
    asm("mov.b64 {%0, %1}, %2;" : "=f"(lo), "=f"(hi) : "l"(in))
#define ADD_F32X2(out, a, b) \
    asm("add.rn.f32x2 %0, %1, %2;" : "=l"(out) : "l"(a), "l"(b))
#define MUL_F32X2(out, a, b) \
    asm("mul.rn.f32x2 %0, %1, %2;" : "=l"(out) : "l"(a), "l"(b))
#define FMA_F32X2(out, a, b, c) \
    asm("fma.rn.f32x2 %0, %1, %2, %3;" : "=l"(out) : "l"(a), "l"(b), "l"(c))

typedef unsigned long long u64;
typedef unsigned int u32;

__device__ __align__(16) float g_newxyz[B_*S_*3];
__device__ int   g_idx[B_*S_*K_];
__device__ __align__(16) float g_ptsT[(size_t)B_*N_*C_];
__device__ float g_pnorm[B_*N_];
__device__ __align__(16) float g_Ybuf[(size_t)M_*CO_];
__device__ __align__(16) float g_Xbuf[(size_t)M_*CO_];
__device__ __align__(16) float g_Hbuf[(size_t)M_*CO_];
__device__ __align__(16) float g_Zbuf[(size_t)M_*CO_];
__device__ __align__(16) float g_Wp[CO_*KP0_];
__device__ __align__(16) float g_sum[CO_];
__device__ __align__(16) float g_sq[CO_];
__device__ __align__(16) float g_scaleL[5*CO_];
__device__ __align__(16) float g_shiftL[5*CO_];

__device__ __forceinline__ void mma_bf16(float* d, u32 a0,u32 a1,u32 a2,u32 a3, u32 b0,u32 b1){
    asm("mma.sync.aligned.m16n8k16.row.col.f32.bf16.bf16.f32 "
        "{%0,%1,%2,%3},{%4,%5,%6,%7},{%8,%9},{%0,%1,%2,%3};"
        : "+f"(d[0]),"+f"(d[1]),"+f"(d[2]),"+f"(d[3])
        : "r"(a0),"r"(a1),"r"(a2),"r"(a3),"r"(b0),"r"(b1));
}
// pack two floats into bf16x2 {lo16=even, hi16=odd} and produce fp32 residuals
__device__ __forceinline__ void split_bf16(float e, float o, u32& hi, u32& lo){
    __nv_bfloat162 h2=__floats2bfloat162_rn(e,o);
    hi=*reinterpret_cast<u32*>(&h2);
    float ef=__uint_as_float(hi<<16);
    float of=__uint_as_float(hi&0xffff0000u);
    __nv_bfloat162 l2=__floats2bfloat162_rn(e-ef,o-of);
    lo=*reinterpret_cast<u32*>(&l2);
}

__global__ void transpose_pts(const float* __restrict__ pts){
    __shared__ float tile[32][33];
    int b=blockIdx.z, n0=blockIdx.x<<5, c0=blockIdx.y<<5;
    int tx=threadIdx.x, ty=threadIdx.y;
    tile[ty][tx]=pts[((size_t)b*C_+(c0+ty))*N_+n0+tx];
    __syncthreads();
    g_ptsT[((size_t)b*N_+(n0+ty))*C_+c0+tx]=tile[tx][ty];
}

__global__ void pnorm_kernel(const float* __restrict__ xyz){
    int id=blockIdx.x*blockDim.x+threadIdx.x;
    if(id>=B_*N_) return;
    int b=id/N_, n=id%N_;
    const float* Xp=xyz+(size_t)b*3*N_;
    float x=Xp[n], y=Xp[N_+n], z=Xp[2*N_+n];
    g_pnorm[id]=fmaf(z,z,fmaf(x,x,y*y));
}

__global__ void wpad_kernel(const float* __restrict__ w){
    int id=blockIdx.x*blockDim.x+threadIdx.x;
    if(id<CO_){ g_sum[id]=0.f; g_sq[id]=0.f; }
    if(id>=CO_*KP0_) return;
    int o=id/KP0_, k=id%KP0_;
    g_Wp[id]=(k<67)?w[o*67+k]:0.0f;
}

__global__ void __launch_bounds__(512,1) fps_kernel(const float* __restrict__ xyz,
                                                    float* __restrict__ out0){
    extern __shared__ u64 fsmu[];
    const int b=blockIdx.x, t=threadIdx.x;
    const float* Xp=xyz+(size_t)b*3*N_;
    u64* sxu=fsmu;
    u64* syu=fsmu+8192;
    u64* szu=fsmu+16384;
    __shared__ int s_bmax[2];
    __shared__ int s_win[2];

    u64 rx[8], ry[8], rz[8];
    float dmin[32];
#pragma unroll
    for(int j=0;j<16;j++){
        int n=j*512+t;
        float x0=Xp[n],        x1=Xp[n+8192];
        float y0=Xp[N_+n],     y1=Xp[N_+n+8192];
        float z0=Xp[2*N_+n],   z1=Xp[2*N_+n+8192];
        u64 px,py,pz;
        PACK_F32X2(px,x0,x1); PACK_F32X2(py,y0,y1); PACK_F32X2(pz,z0,z1);
        sxu[n]=px; syu[n]=py; szu[n]=pz;
        if(j<8){ rx[j]=px; ry[j]=py; rz[j]=pz; }
        dmin[2*j]=1e10f; dmin[2*j+1]=1e10f;
    }
    float cx=Xp[0], cy=Xp[N_], cz=Xp[2*N_];
    if(t==0){
        out0[(size_t)b*3*S_+0]      =cx;
        out0[(size_t)b*3*S_+S_+0]   =cy;
        out0[(size_t)b*3*S_+2*S_+0] =cz;
        float* nz=g_newxyz+(size_t)b*S_*3;
        nz[0]=cx; nz[1]=cy; nz[2]=cz;
        s_bmax[0]=0; s_bmax[1]=0;
        s_win[0]=0x7fffffff; s_win[1]=0x7fffffff;
    }
    __syncthreads();

    const int lane=t&31;
    int p=0;
    for(int it=0; it<S_-1; ++it){
        float ncx=-cx, ncy=-cy, ncz=-cz;
        u64 ncx2,ncy2,ncz2;
        PACK_F32X2(ncx2,ncx,ncx); PACK_F32X2(ncy2,ncy,ncy); PACK_F32X2(ncz2,ncz,ncz);
        float bv=0.0f;
#pragma unroll
        for(int j=0;j<8;j++){
            u64 dx,dy,dz,tt,dd;
            ADD_F32X2(dx,rx[j],ncx2);
            ADD_F32X2(dy,ry[j],ncy2);
            ADD_F32X2(dz,rz[j],ncz2);
            MUL_F32X2(tt,dy,dy);
            FMA_F32X2(tt,dx,dx,tt);
            FMA_F32X2(dd,dz,dz,tt);
            float d0,d1; UNPACK_F32X2(d0,d1,dd);
            float m0=fminf(dmin[2*j],d0);   dmin[2*j]=m0;
            float m1=fminf(dmin[2*j+1],d1); dmin[2*j+1]=m1;
            bv=fmaxf(bv,m0); bv=fmaxf(bv,m1);
        }
#pragma unroll
        for(int j=8;j<16;j++){
            int n=j*512+t;
            u64 dx,dy,dz,tt,dd;
            ADD_F32X2(dx,sxu[n],ncx2);
            ADD_F32X2(dy,syu[n],ncy2);
            ADD_F32X2(dz,szu[n],ncz2);
            MUL_F32X2(tt,dy,dy);
            FMA_F32X2(tt,dx,dx,tt);
            FMA_F32X2(dd,dz,dz,tt);
            float d0,d1; UNPACK_F32X2(d0,d1,dd);
            float m0=fminf(dmin[2*j],d0);   dmin[2*j]=m0;
            float m1=fminf(dmin[2*j+1],d1); dmin[2*j+1]=m1;
            bv=fmaxf(bv,m0); bv=fmaxf(bv,m1);
        }
#pragma unroll
        for(int off=16; off>0; off>>=1)
            bv=fmaxf(bv,__shfl_xor_sync(0xffffffffu,bv,off));
        if(lane==0) atomicMax(&s_bmax[p], __float_as_int(bv));
        __syncthreads();
        const float bmax=__int_as_float(s_bmax[p]);
        if(bv==bmax){
            int cand=0x7fffffff;
#pragma unroll
            for(int k=0;k<32;k++){
                int idx=(k>>1)*512+t+((k&1)<<13);
                if(dmin[k]==bmax) cand=min(cand,idx);
            }
#pragma unroll
            for(int off=16; off>0; off>>=1)
                cand=min(cand,__shfl_xor_sync(0xffffffffu,cand,off));
            if(lane==0) atomicMin(&s_win[p],cand);
        }
        __syncthreads();
        const int w=s_win[p];
        int n=w&8191, hi=w>>13;
        float a0,a1;
        UNPACK_F32X2(a0,a1,sxu[n]); cx = hi? a1:a0;
        UNPACK_F32X2(a0,a1,syu[n]); cy = hi? a1:a0;
        UNPACK_F32X2(a0,a1,szu[n]); cz = hi? a1:a0;
        if(t==0){ s_bmax[p^1]=0; s_win[p^1]=0x7fffffff; }
        if(t==32){
            out0[(size_t)b*3*S_+(it+1)]       =cx;
            out0[(size_t)b*3*S_+S_+(it+1)]    =cy;
            out0[(size_t)b*3*S_+2*S_+(it+1)]  =cz;
            float* nz=g_newxyz+((size_t)b*S_+(it+1))*3;
            nz[0]=cx; nz[1]=cy; nz[2]=cz;
        }
        p^=1;
    }
}

__global__ void query_kernel(const float* __restrict__ xyz){
    int gw=(blockIdx.x*blockDim.x+threadIdx.x)>>5;
    int lane=threadIdx.x&31;
    if(gw>=B_*S_) return;
    int b=gw/S_;
    const float* nz=g_newxyz+(size_t)gw*3;
    float cx=nz[0],cy=nz[1],cz=nz[2];
    float srcn=fmaf(cz,cz,fmaf(cx,cx,cy*cy));
    const float* Xp=xyz+(size_t)b*3*N_;
    const float* pn=g_pnorm+(size_t)b*N_;
    int* dst=g_idx+(size_t)gw*K_;
    int count=0, first=0; bool haveFirst=false;
    for(int base=0; base<N_; base+=32){
        int n=base+lane;
        float dot=fmaf(cz,Xp[2*N_+n],fmaf(cy,Xp[N_+n],cx*Xp[n]));
        float d=fmaf(-2.0f,dot,srcn)+pn[n];
        bool ok=!(d>0.04f);
        unsigned m=__ballot_sync(0xffffffffu,ok);
        if(m){
            if(!haveFirst){first=base+__ffs(m)-1; haveFirst=true;}
            int rank=__popc(m&((1u<<lane)-1u));
            if(ok&&(count+rank)<K_) dst[count+rank]=n;
            count+=__popc(m);
            if(count>=K_) break;
        }
    }
    if(count<K_){
        for(int sl=count+lane; sl<K_; sl+=32) dst[sl]=first;
    }
}

// 3xBF16 tensor-core GEMM (m16n8k16). MODE: 0=raw A, 1=bn+relu on A,
// 2=gather-build A, 3=A=relu(bnA(a)+relu(bnB(a0))). Fused BN stats.
#define BKP2 136
template<int K, int MODE>
__global__ void __launch_bounds__(256,2) gemm_kernel(const float* __restrict__ A,
                                                     const float* __restrict__ W,
                                                     float* __restrict__ Y,
                                                     const float* __restrict__ xyz,
                                                     const float* __restrict__ scA,
                                                     const float* __restrict__ shA,
                                                     const float* __restrict__ A0,
                                                     const float* __restrict__ scB,
                                                     const float* __restrict__ shB){
    __shared__ u32 Abh[2][8][BKP2];
    __shared__ u32 Abl[2][8][BKP2];
    __shared__ u32 Bbh[2][8][BKP2];
    __shared__ u32 Bbl[2][8][BKP2];
    __shared__ float sred[256];
    const int tid=threadIdx.x, m0=blockIdx.x<<7;
    const int lrow=tid>>1, lcol=(tid&1)<<3;   // 128 rows, k-offset 0 or 8
    const int row=m0+lrow;
    const int wid=tid>>5, lane=tid&31;
    const int wm=(wid&3)<<5, wn=(wid>>2)<<6;
    const int g=lane>>2, tg=lane&3;

    sred[tid]=0.f;

    const float* gsrc=nullptr; const float* xp=nullptr;
    float ncx=0.f,ncy=0.f,ncz=0.f; int jj=0;
    if(MODE==2){
        jj=g_idx[row];
        int bidx=row>>16;
        int cent=row>>5;
        ncx=g_newxyz[cent*3+0]; ncy=g_newxyz[cent*3+1]; ncz=g_newxyz[cent*3+2];
        gsrc=g_ptsT+((size_t)bidx*N_+jj)*C_;
        xp=xyz+(size_t)bidx*3*N_;
    }
    const float* Aptr=A+(size_t)row*K+lcol;
    const float* A0ptr=(MODE==3)? A0+(size_t)row*K+lcol : nullptr;
    const float* Wptr=W+(size_t)lrow*K+lcol;

    // load 4 consecutive k starting at absolute k index (k0+lcol+off)
    auto loadA4=[&](int k0,int off)->float4{
        if(MODE==2){
            float v[4];
#pragma unroll
            for(int q=0;q<4;q++){
                int c=k0+lcol+off+q;
                float t;
                if(c<3){ float nn=(c==0)?ncx:((c==1)?ncy:ncz); t=xp[(size_t)c*N_+jj]-nn; }
                else if(c<67) t=gsrc[c-3];
                else t=0.f;
                v[q]=t;
            }
            return make_float4(v[0],v[1],v[2],v[3]);
        }else{
            float4 a=*reinterpret_cast<const float4*>(Aptr+k0+off);
            if(MODE==1){
                int c=k0+lcol+off;
                float4 sc=*reinterpret_cast<const float4*>(&scA[c]);
                float4 sh=*reinterpret_cast<const float4*>(&shA[c]);
                a.x=fmaxf(0.f,fmaf(a.x,sc.x,sh.x));
                a.y=fmaxf(0.f,fmaf(a.y,sc.y,sh.y));
                a.z=fmaxf(0.f,fmaf(a.z,sc.z,sh.z));
                a.w=fmaxf(0.f,fmaf(a.w,sc.w,sh.w));
            }else if(MODE==3){
                int c=k0+lcol+off;
                float4 a0=*reinterpret_cast<const float4*>(A0ptr+k0+off);
                float4 sc=*reinterpret_cast<const float4*>(&scA[c]);
                float4 sh=*reinterpret_cast<const float4*>(&shA[c]);
                float4 s0=*reinterpret_cast<const float4*>(&scB[c]);
                float4 h0=*reinterpret_cast<const float4*>(&shB[c]);
                float x0=fmaxf(0.f,fmaf(a0.x,s0.x,h0.x));
                float x1=fmaxf(0.f,fmaf(a0.y,s0.y,h0.y));
                float x2=fmaxf(0.f,fmaf(a0.z,s0.z,h0.z));
                float x3=fmaxf(0.f,fmaf(a0.w,s0.w,h0.w));
                a.x=fmaxf(0.f,fmaf(a.x,sc.x,sh.x)+x0);
                a.y=fmaxf(0.f,fmaf(a.y,sc.y,sh.y)+x1);
                a.z=fmaxf(0.f,fmaf(a.z,sc.z,sh.z)+x2);
                a.w=fmaxf(0.f,fmaf(a.w,sc.w,sh.w)+x3);
            }
            return a;
        }
    };

    auto stage=[&](int buf, float4 a0v, float4 a1v, float4 w0v, float4 w1v){
        const int kp0=lcol>>1;   // 0 or 4
        u32 h,l;
        split_bf16(a0v.x,a0v.y,h,l); Abh[buf][kp0  ][lrow]=h; Abl[buf][kp0  ][lrow]=l;
        split_bf16(a0v.z,a0v.w,h,l); Abh[buf][kp0+1][lrow]=h; Abl[buf][kp0+1][lrow]=l;
        split_bf16(a1v.x,a1v.y,h,l); Abh[buf][kp0+2][lrow]=h; Abl[buf][kp0+2][lrow]=l;
        split_bf16(a1v.z,a1v.w,h,l); Abh[buf][kp0+3][lrow]=h; Abl[buf][kp0+3][lrow]=l;
        split_bf16(w0v.x,w0v.y,h,l); Bbh[buf][kp0  ][lrow]=h; Bbl[buf][kp0  ][lrow]=l;
        split_bf16(w0v.z,w0v.w,h,l); Bbh[buf][kp0+1][lrow]=h; Bbl[buf][kp0+1][lrow]=l;
        split_bf16(w1v.x,w1v.y,h,l); Bbh[buf][kp0+2][lrow]=h; Bbl[buf][kp0+2][lrow]=l;
        split_bf16(w1v.z,w1v.w,h,l); Bbh[buf][kp0+3][lrow]=h; Bbl[buf][kp0+3][lrow]=l;
    };

    float d[2][8][4];
#pragma unroll
    for(int mt=0;mt<2;mt++)
#pragma unroll
        for(int nt=0;nt<8;nt++)
#pragma unroll
            for(int q=0;q<4;q++) d[mt][nt][q]=0.f;

    constexpr int NT=K/16;
    float4 a0v=loadA4(0,0), a1v=loadA4(0,4);
    float4 w0v=*reinterpret_cast<const float4*>(Wptr);
    float4 w1v=*reinterpret_cast<const float4*>(Wptr+4);
    stage(0,a0v,a1v,w0v,w1v);
    __syncthreads();

    for(int it=0; it<NT; ++it){
        const int cur=it&1;
        if(it+1<NT){
            a0v=loadA4((it+1)*16,0); a1v=loadA4((it+1)*16,4);
            w0v=*reinterpret_cast<const float4*>(Wptr+(it+1)*16);
            w1v=*reinterpret_cast<const float4*>(Wptr+(it+1)*16+4);
        }
        u32 ah[2][4], al[2][4];
#pragma unroll
        for(int mt=0;mt<2;mt++){
            int r0=wm+(mt<<4)+g;
            ah[mt][0]=Abh[cur][tg  ][r0];
            ah[mt][1]=Abh[cur][tg  ][r0+8];
            ah[mt][2]=Abh[cur][tg+4][r0];
            ah[mt][3]=Abh[cur][tg+4][r0+8];
            al[mt][0]=Abl[cur][tg  ][r0];
            al[mt][1]=Abl[cur][tg  ][r0+8];
            al[mt][2]=Abl[cur][tg+4][r0];
            al[mt][3]=Abl[cur][tg+4][r0+8];
        }
#pragma unroll
        for(int nt=0;nt<8;nt++){
            int nn=wn+(nt<<3)+g;
            u32 bh0=Bbh[cur][tg  ][nn];
            u32 bh1=Bbh[cur][tg+4][nn];
            u32 bl0=Bbl[cur][tg  ][nn];
            u32 bl1=Bbl[cur][tg+4][nn];
#pragma unroll
            for(int mt=0;mt<2;mt++){
                mma_bf16(d[mt][nt], ah[mt][0],ah[mt][1],ah[mt][2],ah[mt][3], bh0,bh1);
                mma_bf16(d[mt][nt], ah[mt][0],ah[mt][1],ah[mt][2],ah[mt][3], bl0,bl1);
                mma_bf16(d[mt][nt], al[mt][0],al[mt][1],al[mt][2],al[mt][3], bh0,bh1);
            }
        }
        if(it+1<NT) stage(cur^1,a0v,a1v,w0v,w1v);
        __syncthreads();
    }

    float cs[8][2], cq[8][2];
#pragma unroll
    for(int nt=0;nt<8;nt++){ cs[nt][0]=0.f; cs[nt][1]=0.f; cq[nt][0]=0.f; cq[nt][1]=0.f; }
#pragma unroll
    for(int nt=0;nt<8;nt++){
        int nbase=wn+(nt<<3)+(tg<<1);
#pragma unroll
        for(int mt=0;mt<2;mt++){
            int mlo=m0+wm+(mt<<4)+g;
            float d0=d[mt][nt][0], d1=d[mt][nt][1], d2=d[mt][nt][2], d3=d[mt][nt][3];
            *reinterpret_cast<float2*>(&Y[(size_t)mlo*CO_+nbase])    =make_float2(d0,d1);
            *reinterpret_cast<float2*>(&Y[(size_t)(mlo+8)*CO_+nbase])=make_float2(d2,d3);
            cs[nt][0]+=d0+d2; cs[nt][1]+=d1+d3;
            cq[nt][0]=fmaf(d0,d0,cq[nt][0]); cq[nt][0]=fmaf(d2,d2,cq[nt][0]);
            cq[nt][1]=fmaf(d1,d1,cq[nt][1]); cq[nt][1]=fmaf(d3,d3,cq[nt][1]);
        }
    }
#pragma unroll
    for(int off=4; off<32; off<<=1){
#pragma unroll
        for(int nt=0;nt<8;nt++){
            cs[nt][0]+=__shfl_xor_sync(0xffffffffu,cs[nt][0],off);
            cs[nt][1]+=__shfl_xor_sync(0xffffffffu,cs[nt][1],off);
            cq[nt][0]+=__shfl_xor_sync(0xffffffffu,cq[nt][0],off);
            cq[nt][1]+=__shfl_xor_sync(0xffffffffu,cq[nt][1],off);
        }
    }
    if(lane<4){
#pragma unroll
        for(int nt=0;nt<8;nt++){
            int col=wn+(nt<<3)+(lane<<1);
            atomicAdd(&sred[col],     cs[nt][0]);
            atomicAdd(&sred[col+1],   cs[nt][1]);
            atomicAdd(&sred[128+col],   cq[nt][0]);
            atomicAdd(&sred[128+col+1], cq[nt][1]);
        }
    }
    __syncthreads();
    if(tid<128){
        atomicAdd(&g_sum[tid], sred[tid]);
        atomicAdd(&g_sq[tid],  sred[128+tid]);
    }
}

__global__ void finalize_kernel(const float* __restrict__ gg, const float* __restrict__ bb,
                                float* __restrict__ sc_out, float* __restrict__ sh_out){
    int c=threadIdx.x;
    if(c<CO_){
        const float inv=1.0f/(float)M_;
        float mu=g_sum[c]*inv;
        float var=g_sq[c]*inv-mu*mu;
        float rs=rsqrtf(var+1e-5f);
        float sc=gg[c]*rs;
        sc_out[c]=sc;
        sh_out[c]=bb[c]-mu*sc;
        g_sum[c]=0.f; g_sq[c]=0.f;
    }
}

__global__ void maxpool3_kernel(const float* __restrict__ Y4, const float* __restrict__ Y2,
                                const float* __restrict__ Y0, float* __restrict__ out2,
                                const float* __restrict__ scL, const float* __restrict__ shL){
    int id=blockIdx.x*blockDim.x+threadIdx.x;
    int c=id&127;
    int s=(id>>7)&(S_-1);
    int b=id>>18;
    size_t base=((size_t)(b*S_+s)*K_)*CO_+c;
    float sc0=scL[0*CO_+c], sh0=shL[0*CO_+c];
    float sc2=scL[2*CO_+c], sh2=shL[2*CO_+c];
    float sc4=scL[4*CO_+c], sh4=shL[4*CO_+c];
    float m=-1e30f;
#pragma unroll
    for(int k=0;k<K_;k++){
        size_t o=base+(size_t)k*CO_;
        float x0=fmaxf(0.f,fmaf(Y0[o],sc0,sh0));
        float xr=fmaxf(0.f,fmaf(Y2[o],sc2,sh2)+x0);
        float v =fmaxf(0.f,fmaf(Y4[o],sc4,sh4)+xr);
        m=fmaxf(m,v);
    }
    out2[((size_t)b*CO_+c)*S_+s]=m;
}

extern "C" void kernel_launch(void* const* d_in, const int* in_sizes, int n_in,
                              void* d_out, int out_size){
    const float* xyz  =(const float*)d_in[0];
    const float* pts  =(const float*)d_in[1];
    const float* wproj=(const float*)d_in[2];
    const float* gproj=(const float*)d_in[3];
    const float* bproj=(const float*)d_in[4];
    const float* w1   =(const float*)d_in[5];
    const float* w2   =(const float*)d_in[6];
    const float* g1   =(const float*)d_in[7];
    const float* b1   =(const float*)d_in[8];
    const float* g2   =(const float*)d_in[9];
    const float* b2   =(const float*)d_in[10];
    float* out=(float*)d_out;

    void *pYv,*pXv,*pHv,*pZv,*pWpv,*pScv,*pShv;
    cudaGetSymbolAddress(&pYv, g_Ybuf);
    cudaGetSymbolAddress(&pXv, g_Xbuf);
    cudaGetSymbolAddress(&pHv, g_Hbuf);
    cudaGetSymbolAddress(&pZv, g_Zbuf);
    cudaGetSymbolAddress(&pWpv,g_Wp);
    cudaGetSymbolAddress(&pScv,g_scaleL);
    cudaGetSymbolAddress(&pShv,g_shiftL);
    float* pY=(float*)pYv; float* pX=(float*)pXv; float* pH=(float*)pHv;
    float* pZ=(float*)pZv; float* pWp=(float*)pWpv;
    float* scL=(float*)pScv; float* shL=(float*)pShv;

    cudaFuncSetAttribute(fps_kernel, cudaFuncAttributeMaxDynamicSharedMemorySize, 3*8192*8);

    transpose_pts<<<dim3(N_/32, C_/32, B_), dim3(32,32)>>>(pts);
    pnorm_kernel<<<(B_*N_+1023)/1024,1024>>>(xyz);
    wpad_kernel<<<(CO_*KP0_+1023)/1024,1024>>>(wproj);

    fps_kernel<<<B_,512,3*8192*8>>>(xyz,out);
    query_kernel<<<(B_*S_*32)/256,256>>>(xyz);

    const int GG=M_/128;

    gemm_kernel<KP0_,2><<<GG,256>>>(pY, pWp, pY, xyz, scL, shL, nullptr, nullptr, nullptr);
    finalize_kernel<<<1,128>>>(gproj, bproj, scL+0*CO_, shL+0*CO_);

    gemm_kernel<128,1><<<GG,256>>>(pY, w1, pH, xyz, scL+0*CO_, shL+0*CO_, nullptr, nullptr, nullptr);
    finalize_kernel<<<1,128>>>(g1, b1, scL+1*CO_, shL+1*CO_);
    gemm_kernel<128,1><<<GG,256>>>(pH, w2, pX, xyz, scL+1*CO_, shL+1*CO_, nullptr, nullptr, nullptr);
    finalize_kernel<<<1,128>>>(g2, b2, scL+2*CO_, shL+2*CO_);

    gemm_kernel<128,3><<<GG,256>>>(pX, w1+CO_*CO_, pZ, xyz,
                                   scL+2*CO_, shL+2*CO_, pY, scL+0*CO_, shL+0*CO_);
    finalize_kernel<<<1,128>>>(g1+CO_, b1+CO_, scL+3*CO_, shL+3*CO_);
    gemm_kernel<128,1><<<GG,256>>>(pZ, w2+CO_*CO_, pH, xyz, scL+3*CO_, shL+3*CO_, nullptr, nullptr, nullptr);
    finalize_kernel<<<1,128>>>(g2+CO_, b2+CO_, scL+4*CO_, shL+4*CO_);

    maxpool3_kernel<<<(B_*S_*CO_)/256,256>>>(pH, pX, pY, out + B_*3*S_, scL, shL);
}

// round 15
// speedup vs baseline: 1.6430x; 1.0246x over previous
#include <cuda_runtime.h>
#include <cuda_bf16.h>
#include <cstdint>

#define B_   4
#define N_   16384
#define C_   64
#define S_   2048
#define K_   32
#define M_   (B_*S_*K_)
#define CO_  128
#define KP0_ 80

#define PACK_F32X2(out, lo, hi) \
    asm("mov.b64 %0, {%1, %2};" : "=l"(out) : "f"(lo), "f"(hi))
#define UNPACK_F32X2(lo, hi, in) \
    asm("mov.b64 {%0, %1}, %2;" : "=f"(lo), "=f"(hi) : "l"(in))
#define ADD_F32X2(out, a, b) \
    asm("add.rn.f32x2 %0, %1, %2;" : "=l"(out) : "l"(a), "l"(b))
#define MUL_F32X2(out, a, b) \
    asm("mul.rn.f32x2 %0, %1, %2;" : "=l"(out) : "l"(a), "l"(b))
#define FMA_F32X2(out, a, b, c) \
    asm("fma.rn.f32x2 %0, %1, %2, %3;" : "=l"(out) : "l"(a), "l"(b), "l"(c))

typedef unsigned long long u64;
typedef unsigned int u32;

__device__ __align__(16) float g_newxyz[B_*S_*3];
__device__ int   g_idx[B_*S_*K_];
__device__ __align__(16) float g_ptsT[(size_t)B_*N_*C_];
__device__ float g_pnorm[B_*N_];
__device__ __align__(16) float g_Ybuf[(size_t)M_*CO_];
__device__ __align__(16) float g_Xbuf[(size_t)M_*CO_];
__device__ __align__(16) float g_Hbuf[(size_t)M_*CO_];
__device__ __align__(16) float g_Zbuf[(size_t)M_*CO_];
__device__ __align__(16) float g_Wp[CO_*KP0_];
__device__ __align__(16) float g_sum[CO_];
__device__ __align__(16) float g_sq[CO_];
__device__ __align__(16) float g_scaleL[5*CO_];
__device__ __align__(16) float g_shiftL[5*CO_];

__device__ __forceinline__ void mma_bf16(float* d, u32 a0,u32 a1,u32 a2,u32 a3, u32 b0,u32 b1){
    asm("mma.sync.aligned.m16n8k16.row.col.f32.bf16.bf16.f32 "
        "{%0,%1,%2,%3},{%4,%5,%6,%7},{%8,%9},{%0,%1,%2,%3};"
        : "+f"(d[0]),"+f"(d[1]),"+f"(d[2]),"+f"(d[3])
        : "r"(a0),"r"(a1),"r"(a2),"r"(a3),"r"(b0),"r"(b1));
}
__device__ __forceinline__ void split_bf16(float e, float o, u32& hi, u32& lo){
    __nv_bfloat162 h2=__floats2bfloat162_rn(e,o);
    hi=*reinterpret_cast<u32*>(&h2);
    float ef=__uint_as_float(hi<<16);
    float of=__uint_as_float(hi&0xffff0000u);
    __nv_bfloat162 l2=__floats2bfloat162_rn(e-ef,o-of);
    lo=*reinterpret_cast<u32*>(&l2);
}

__global__ void transpose_pts(const float* __restrict__ pts){
    __shared__ float tile[32][33];
    int b=blockIdx.z, n0=blockIdx.x<<5, c0=blockIdx.y<<5;
    int tx=threadIdx.x, ty=threadIdx.y;
    tile[ty][tx]=pts[((size_t)b*C_+(c0+ty))*N_+n0+tx];
    __syncthreads();
    g_ptsT[((size_t)b*N_+(n0+ty))*C_+c0+tx]=tile[tx][ty];
}

__global__ void pnorm_kernel(const float* __restrict__ xyz){
    int id=blockIdx.x*blockDim.x+threadIdx.x;
    if(id>=B_*N_) return;
    int b=id/N_, n=id%N_;
    const float* Xp=xyz+(size_t)b*3*N_;
    float x=Xp[n], y=Xp[N_+n], z=Xp[2*N_+n];
    g_pnorm[id]=fmaf(z,z,fmaf(x,x,y*y));
}

__global__ void wpad_kernel(const float* __restrict__ w){
    int id=blockIdx.x*blockDim.x+threadIdx.x;
    if(id<CO_){ g_sum[id]=0.f; g_sq[id]=0.f; }
    if(id>=CO_*KP0_) return;
    int o=id/KP0_, k=id%KP0_;
    g_Wp[id]=(k<67)?w[o*67+k]:0.0f;
}

// FPS: 512 thr/block, 1 block/batch. Pairs (n, n+8192) packed f32x2.
// Pairs 0-7: xyz regs. Pairs 8-11: x,y regs + z smem. Pairs 12-15: smem.
__global__ void __launch_bounds__(512,1) fps_kernel(const float* __restrict__ xyz,
                                                    float* __restrict__ out0){
    extern __shared__ u64 fsmu[];
    const int b=blockIdx.x, t=threadIdx.x;
    const float* Xp=xyz+(size_t)b*3*N_;
    u64* sxu=fsmu;
    u64* syu=fsmu+8192;
    u64* szu=fsmu+16384;
    __shared__ int s_bmax[2];
    __shared__ int s_win[2];

    u64 rx[8], ry[8], rz[8];
    u64 qx[4], qy[4];
    float dmin[32];
#pragma unroll
    for(int j=0;j<16;j++){
        int n=j*512+t;
        float x0=Xp[n],        x1=Xp[n+8192];
        float y0=Xp[N_+n],     y1=Xp[N_+n+8192];
        float z0=Xp[2*N_+n],   z1=Xp[2*N_+n+8192];
        u64 px,py,pz;
        PACK_F32X2(px,x0,x1); PACK_F32X2(py,y0,y1); PACK_F32X2(pz,z0,z1);
        sxu[n]=px; syu[n]=py; szu[n]=pz;
        if(j<8){ rx[j]=px; ry[j]=py; rz[j]=pz; }
        else if(j<12){ qx[j-8]=px; qy[j-8]=py; }
        dmin[2*j]=1e10f; dmin[2*j+1]=1e10f;
    }
    float cx=Xp[0], cy=Xp[N_], cz=Xp[2*N_];
    if(t==0){
        out0[(size_t)b*3*S_+0]      =cx;
        out0[(size_t)b*3*S_+S_+0]   =cy;
        out0[(size_t)b*3*S_+2*S_+0] =cz;
        float* nz=g_newxyz+(size_t)b*S_*3;
        nz[0]=cx; nz[1]=cy; nz[2]=cz;
        s_bmax[0]=0; s_bmax[1]=0;
        s_win[0]=0x7fffffff; s_win[1]=0x7fffffff;
    }
    __syncthreads();

    const int lane=t&31;
    int p=0;
    for(int it=0; it<S_-1; ++it){
        float ncx=-cx, ncy=-cy, ncz=-cz;
        u64 ncx2,ncy2,ncz2;
        PACK_F32X2(ncx2,ncx,ncx); PACK_F32X2(ncy2,ncy,ncy); PACK_F32X2(ncz2,ncz,ncz);
        float bv=0.0f;
#pragma unroll
        for(int j=0;j<8;j++){
            u64 dx,dy,dz,tt,dd;
            ADD_F32X2(dx,rx[j],ncx2);
            ADD_F32X2(dy,ry[j],ncy2);
            ADD_F32X2(dz,rz[j],ncz2);
            MUL_F32X2(tt,dy,dy);
            FMA_F32X2(tt,dx,dx,tt);
            FMA_F32X2(dd,dz,dz,tt);
            float d0,d1; UNPACK_F32X2(d0,d1,dd);
            float m0=fminf(dmin[2*j],d0);   dmin[2*j]=m0;
            float m1=fminf(dmin[2*j+1],d1); dmin[2*j+1]=m1;
            bv=fmaxf(bv,m0); bv=fmaxf(bv,m1);
        }
#pragma unroll
        for(int j=8;j<12;j++){
            int n=j*512+t;
            u64 dx,dy,dz,tt,dd;
            ADD_F32X2(dx,qx[j-8],ncx2);
            ADD_F32X2(dy,qy[j-8],ncy2);
            ADD_F32X2(dz,szu[n],ncz2);
            MUL_F32X2(tt,dy,dy);
            FMA_F32X2(tt,dx,dx,tt);
            FMA_F32X2(dd,dz,dz,tt);
            float d0,d1; UNPACK_F32X2(d0,d1,dd);
            float m0=fminf(dmin[2*j],d0);   dmin[2*j]=m0;
            float m1=fminf(dmin[2*j+1],d1); dmin[2*j+1]=m1;
            bv=fmaxf(bv,m0); bv=fmaxf(bv,m1);
        }
#pragma unroll
        for(int j=12;j<16;j++){
            int n=j*512+t;
            u64 dx,dy,dz,tt,dd;
            ADD_F32X2(dx,sxu[n],ncx2);
            ADD_F32X2(dy,syu[n],ncy2);
            ADD_F32X2(dz,szu[n],ncz2);
            MUL_F32X2(tt,dy,dy);
            FMA_F32X2(tt,dx,dx,tt);
            FMA_F32X2(dd,dz,dz,tt);
            float d0,d1; UNPACK_F32X2(d0,d1,dd);
            float m0=fminf(dmin[2*j],d0);   dmin[2*j]=m0;
            float m1=fminf(dmin[2*j+1],d1); dmin[2*j+1]=m1;
            bv=fmaxf(bv,m0); bv=fmaxf(bv,m1);
        }
#pragma unroll
        for(int off=16; off>0; off>>=1)
            bv=fmaxf(bv,__shfl_xor_sync(0xffffffffu,bv,off));
        if(lane==0) atomicMax(&s_bmax[p], __float_as_int(bv));
        __syncthreads();
        const float bmax=__int_as_float(s_bmax[p]);
        if(bv==bmax){
            int cand=0x7fffffff;
#pragma unroll
            for(int k=0;k<32;k++){
                int idx=(k>>1)*512+t+((k&1)<<13);
                if(dmin[k]==bmax) cand=min(cand,idx);
            }
#pragma unroll
            for(int off=16; off>0; off>>=1)
                cand=min(cand,__shfl_xor_sync(0xffffffffu,cand,off));
            if(lane==0) atomicMin(&s_win[p],cand);
        }
        __syncthreads();
        const int w=s_win[p];
        int n=w&8191, hi=w>>13;
        float a0,a1;
        UNPACK_F32X2(a0,a1,sxu[n]); cx = hi? a1:a0;
        UNPACK_F32X2(a0,a1,syu[n]); cy = hi? a1:a0;
        UNPACK_F32X2(a0,a1,szu[n]); cz = hi? a1:a0;
        if(t==0){ s_bmax[p^1]=0; s_win[p^1]=0x7fffffff; }
        if(t==32){
            out0[(size_t)b*3*S_+(it+1)]       =cx;
            out0[(size_t)b*3*S_+S_+(it+1)]    =cy;
            out0[(size_t)b*3*S_+2*S_+(it+1)]  =cz;
            float* nz=g_newxyz+((size_t)b*S_+(it+1))*3;
            nz[0]=cx; nz[1]=cy; nz[2]=cz;
        }
        p^=1;
    }
}

__global__ void query_kernel(const float* __restrict__ xyz){
    int gw=(blockIdx.x*blockDim.x+threadIdx.x)>>5;
    int lane=threadIdx.x&31;
    if(gw>=B_*S_) return;
    int b=gw/S_;
    const float* nz=g_newxyz+(size_t)gw*3;
    float cx=nz[0],cy=nz[1],cz=nz[2];
    float srcn=fmaf(cz,cz,fmaf(cx,cx,cy*cy));
    const float* Xp=xyz+(size_t)b*3*N_;
    const float* pn=g_pnorm+(size_t)b*N_;
    int* dst=g_idx+(size_t)gw*K_;
    int count=0, first=0; bool haveFirst=false;
    for(int base=0; base<N_; base+=32){
        int n=base+lane;
        float dot=fmaf(cz,Xp[2*N_+n],fmaf(cy,Xp[N_+n],cx*Xp[n]));
        float d=fmaf(-2.0f,dot,srcn)+pn[n];
        bool ok=!(d>0.04f);
        unsigned m=__ballot_sync(0xffffffffu,ok);
        if(m){
            if(!haveFirst){first=base+__ffs(m)-1; haveFirst=true;}
            int rank=__popc(m&((1u<<lane)-1u));
            if(ok&&(count+rank)<K_) dst[count+rank]=n;
            count+=__popc(m);
            if(count>=K_) break;
        }
    }
    if(count<K_){
        for(int sl=count+lane; sl<K_; sl+=32) dst[sl]=first;
    }
}

// 3xBF16 tensor-core GEMM (m16n8k16). MODE: 0=raw A, 1=bn+relu on A,
// 2=gather-build A, 3=A=relu(bnA(a)+relu(bnB(a0))). Fused BN stats.
#define BKP2 136
template<int K, int MODE>
__global__ void __launch_bounds__(256,2) gemm_kernel(const float* __restrict__ A,
                                                     const float* __restrict__ W,
                                                     float* __restrict__ Y,
                                                     const float* __restrict__ xyz,
                                                     const float* __restrict__ scA,
                                                     const float* __restrict__ shA,
                                                     const float* __restrict__ A0,
                                                     const float* __restrict__ scB,
                                                     const float* __restrict__ shB){
    __shared__ u32 Abh[2][8][BKP2];
    __shared__ u32 Abl[2][8][BKP2];
    __shared__ u32 Bbh[2][8][BKP2];
    __shared__ u32 Bbl[2][8][BKP2];
    __shared__ float sred[256];
    const int tid=threadIdx.x, m0=blockIdx.x<<7;
    const int lrow=tid>>1, lcol=(tid&1)<<3;
    const int row=m0+lrow;
    const int wid=tid>>5, lane=tid&31;
    const int wm=(wid&3)<<5, wn=(wid>>2)<<6;
    const int g=lane>>2, tg=lane&3;

    sred[tid]=0.f;

    const float* gsrc=nullptr; const float* xp=nullptr;
    float ncx=0.f,ncy=0.f,ncz=0.f; int jj=0;
    if(MODE==2){
        jj=g_idx[row];
        int bidx=row>>16;
        int cent=row>>5;
        ncx=g_newxyz[cent*3+0]; ncy=g_newxyz[cent*3+1]; ncz=g_newxyz[cent*3+2];
        gsrc=g_ptsT+((size_t)bidx*N_+jj)*C_;
        xp=xyz+(size_t)bidx*3*N_;
    }
    const float* Aptr=A+(size_t)row*K+lcol;
    const float* A0ptr=(MODE==3)? A0+(size_t)row*K+lcol : nullptr;
    const float* Wptr=W+(size_t)lrow*K+lcol;

    auto loadA4=[&](int k0,int off)->float4{
        if(MODE==2){
            float v[4];
#pragma unroll
            for(int q=0;q<4;q++){
                int c=k0+lcol+off+q;
                float t;
                if(c<3){ float nn=(c==0)?ncx:((c==1)?ncy:ncz); t=xp[(size_t)c*N_+jj]-nn; }
                else if(c<67) t=gsrc[c-3];
                else t=0.f;
                v[q]=t;
            }
            return make_float4(v[0],v[1],v[2],v[3]);
        }else{
            float4 a=*reinterpret_cast<const float4*>(Aptr+k0+off);
            if(MODE==1){
                int c=k0+lcol+off;
                float4 sc=*reinterpret_cast<const float4*>(&scA[c]);
                float4 sh=*reinterpret_cast<const float4*>(&shA[c]);
                a.x=fmaxf(0.f,fmaf(a.x,sc.x,sh.x));
                a.y=fmaxf(0.f,fmaf(a.y,sc.y,sh.y));
                a.z=fmaxf(0.f,fmaf(a.z,sc.z,sh.z));
                a.w=fmaxf(0.f,fmaf(a.w,sc.w,sh.w));
            }else if(MODE==3){
                int c=k0+lcol+off;
                float4 a0=*reinterpret_cast<const float4*>(A0ptr+k0+off);
                float4 sc=*reinterpret_cast<const float4*>(&scA[c]);
                float4 sh=*reinterpret_cast<const float4*>(&shA[c]);
                float4 s0=*reinterpret_cast<const float4*>(&scB[c]);
                float4 h0=*reinterpret_cast<const float4*>(&shB[c]);
                float x0=fmaxf(0.f,fmaf(a0.x,s0.x,h0.x));
                float x1=fmaxf(0.f,fmaf(a0.y,s0.y,h0.y));
                float x2=fmaxf(0.f,fmaf(a0.z,s0.z,h0.z));
                float x3=fmaxf(0.f,fmaf(a0.w,s0.w,h0.w));
                a.x=fmaxf(0.f,fmaf(a.x,sc.x,sh.x)+x0);
                a.y=fmaxf(0.f,fmaf(a.y,sc.y,sh.y)+x1);
                a.z=fmaxf(0.f,fmaf(a.z,sc.z,sh.z)+x2);
                a.w=fmaxf(0.f,fmaf(a.w,sc.w,sh.w)+x3);
            }
            return a;
        }
    };

    auto stage=[&](int buf, float4 a0v, float4 a1v, float4 w0v, float4 w1v){
        const int kp0=lcol>>1;
        u32 h,l;
        split_bf16(a0v.x,a0v.y,h,l); Abh[buf][kp0  ][lrow]=h; Abl[buf][kp0  ][lrow]=l;
        split_bf16(a0v.z,a0v.w,h,l); Abh[buf][kp0+1][lrow]=h; Abl[buf][kp0+1][lrow]=l;
        split_bf16(a1v.x,a1v.y,h,l); Abh[buf][kp0+2][lrow]=h; Abl[buf][kp0+2][lrow]=l;
        split_bf16(a1v.z,a1v.w,h,l); Abh[buf][kp0+3][lrow]=h; Abl[buf][kp0+3][lrow]=l;
        split_bf16(w0v.x,w0v.y,h,l); Bbh[buf][kp0  ][lrow]=h; Bbl[buf][kp0  ][lrow]=l;
        split_bf16(w0v.z,w0v.w,h,l); Bbh[buf][kp0+1][lrow]=h; Bbl[buf][kp0+1][lrow]=l;
        split_bf16(w1v.x,w1v.y,h,l); Bbh[buf][kp0+2][lrow]=h; Bbl[buf][kp0+2][lrow]=l;
        split_bf16(w1v.z,w1v.w,h,l); Bbh[buf][kp0+3][lrow]=h; Bbl[buf][kp0+3][lrow]=l;
    };

    float d[2][8][4];
#pragma unroll
    for(int mt=0;mt<2;mt++)
#pragma unroll
        for(int nt=0;nt<8;nt++)
#pragma unroll
            for(int q=0;q<4;q++) d[mt][nt][q]=0.f;

    constexpr int NT=K/16;
    float4 a0v=loadA4(0,0), a1v=loadA4(0,4);
    float4 w0v=*reinterpret_cast<const float4*>(Wptr);
    float4 w1v=*reinterpret_cast<const float4*>(Wptr+4);
    stage(0,a0v,a1v,w0v,w1v);
    __syncthreads();

    for(int it=0; it<NT; ++it){
        const int cur=it&1;
        if(it+1<NT){
            a0v=loadA4((it+1)*16,0); a1v=loadA4((it+1)*16,4);
            w0v=*reinterpret_cast<const float4*>(Wptr+(it+1)*16);
            w1v=*reinterpret_cast<const float4*>(Wptr+(it+1)*16+4);
        }
        u32 ah[2][4], al[2][4];
#pragma unroll
        for(int mt=0;mt<2;mt++){
            int r0=wm+(mt<<4)+g;
            ah[mt][0]=Abh[cur][tg  ][r0];
            ah[mt][1]=Abh[cur][tg  ][r0+8];
            ah[mt][2]=Abh[cur][tg+4][r0];
            ah[mt][3]=Abh[cur][tg+4][r0+8];
            al[mt][0]=Abl[cur][tg  ][r0];
            al[mt][1]=Abl[cur][tg  ][r0+8];
            al[mt][2]=Abl[cur][tg+4][r0];
            al[mt][3]=Abl[cur][tg+4][r0+8];
        }
#pragma unroll
        for(int nt=0;nt<8;nt++){
            int nn=wn+(nt<<3)+g;
            u32 bh0=Bbh[cur][tg  ][nn];
            u32 bh1=Bbh[cur][tg+4][nn];
            u32 bl0=Bbl[cur][tg  ][nn];
            u32 bl1=Bbl[cur][tg+4][nn];
#pragma unroll
            for(int mt=0;mt<2;mt++){
                mma_bf16(d[mt][nt], ah[mt][0],ah[mt][1],ah[mt][2],ah[mt][3], bh0,bh1);
                mma_bf16(d[mt][nt], ah[mt][0],ah[mt][1],ah[mt][2],ah[mt][3], bl0,bl1);
                mma_bf16(d[mt][nt], al[mt][0],al[mt][1],al[mt][2],al[mt][3], bh0,bh1);
            }
        }
        if(it+1<NT) stage(cur^1,a0v,a1v,w0v,w1v);
        __syncthreads();
    }

    float cs[8][2], cq[8][2];
#pragma unroll
    for(int nt=0;nt<8;nt++){ cs[nt][0]=0.f; cs[nt][1]=0.f; cq[nt][0]=0.f; cq[nt][1]=0.f; }
#pragma unroll
    for(int nt=0;nt<8;nt++){
        int nbase=wn+(nt<<3)+(tg<<1);
#pragma unroll
        for(int mt=0;mt<2;mt++){
            int mlo=m0+wm+(mt<<4)+g;
            float d0=d[mt][nt][0], d1=d[mt][nt][1], d2=d[mt][nt][2], d3=d[mt][nt][3];
            *reinterpret_cast<float2*>(&Y[(size_t)mlo*CO_+nbase])    =make_float2(d0,d1);
            *reinterpret_cast<float2*>(&Y[(size_t)(mlo+8)*CO_+nbase])=make_float2(d2,d3);
            cs[nt][0]+=d0+d2; cs[nt][1]+=d1+d3;
            cq[nt][0]=fmaf(d0,d0,cq[nt][0]); cq[nt][0]=fmaf(d2,d2,cq[nt][0]);
            cq[nt][1]=fmaf(d1,d1,cq[nt][1]); cq[nt][1]=fmaf(d3,d3,cq[nt][1]);
        }
    }
#pragma unroll
    for(int off=4; off<32; off<<=1){
#pragma unroll
        for(int nt=0;nt<8;nt++){
            cs[nt][0]+=__shfl_xor_sync(0xffffffffu,cs[nt][0],off);
            cs[nt][1]+=__shfl_xor_sync(0xffffffffu,cs[nt][1],off);
            cq[nt][0]+=__shfl_xor_sync(0xffffffffu,cq[nt][0],off);
            cq[nt][1]+=__shfl_xor_sync(0xffffffffu,cq[nt][1],off);
        }
    }
    if(lane<4){
#pragma unroll
        for(int nt=0;nt<8;nt++){
            int col=wn+(nt<<3)+(lane<<1);
            atomicAdd(&sred[col],     cs[nt][0]);
            atomicAdd(&sred[col+1],   cs[nt][1]);
            atomicAdd(&sred[128+col],   cq[nt][0]);
            atomicAdd(&sred[128+col+1], cq[nt][1]);
        }
    }
    __syncthreads();
    if(tid<128){
        atomicAdd(&g_sum[tid], sred[tid]);
        atomicAdd(&g_sq[tid],  sred[128+tid]);
    }
}

__global__ void finalize_kernel(const float* __restrict__ gg, const float* __restrict__ bb,
                                float* __restrict__ sc_out, float* __restrict__ sh_out){
    int c=threadIdx.x;
    if(c<CO_){
        const float inv=1.0f/(float)M_;
        float mu=g_sum[c]*inv;
        float var=g_sq[c]*inv-mu*mu;
        float rs=rsqrtf(var+1e-5f);
        float sc=gg[c]*rs;
        sc_out[c]=sc;
        sh_out[c]=bb[c]-mu*sc;
        g_sum[c]=0.f; g_sq[c]=0.f;
    }
}

__global__ void maxpool3_kernel(const float* __restrict__ Y4, const float* __restrict__ Y2,
                                const float* __restrict__ Y0, float* __restrict__ out2,
                                const float* __restrict__ scL, const float* __restrict__ shL){
    int id=blockIdx.x*blockDim.x+threadIdx.x;
    int c=id&127;
    int s=(id>>7)&(S_-1);
    int b=id>>18;
    size_t base=((size_t)(b*S_+s)*K_)*CO_+c;
    float sc0=scL[0*CO_+c], sh0=shL[0*CO_+c];
    float sc2=scL[2*CO_+c], sh2=shL[2*CO_+c];
    float sc4=scL[4*CO_+c], sh4=shL[4*CO_+c];
    float m=-1e30f;
#pragma unroll
    for(int k=0;k<K_;k++){
        size_t o=base+(size_t)k*CO_;
        float x0=fmaxf(0.f,fmaf(Y0[o],sc0,sh0));
        float xr=fmaxf(0.f,fmaf(Y2[o],sc2,sh2)+x0);
        float v =fmaxf(0.f,fmaf(Y4[o],sc4,sh4)+xr);
        m=fmaxf(m,v);
    }
    out2[((size_t)b*CO_+c)*S_+s]=m;
}

extern "C" void kernel_launch(void* const* d_in, const int* in_sizes, int n_in,
                              void* d_out, int out_size){
    const float* xyz  =(const float*)d_in[0];
    const float* pts  =(const float*)d_in[1];
    const float* wproj=(const float*)d_in[2];
    const float* gproj=(const float*)d_in[3];
    const float* bproj=(const float*)d_in[4];
    const float* w1   =(const float*)d_in[5];
    const float* w2   =(const float*)d_in[6];
    const float* g1   =(const float*)d_in[7];
    const float* b1   =(const float*)d_in[8];
    const float* g2   =(const float*)d_in[9];
    const float* b2   =(const float*)d_in[10];
    float* out=(float*)d_out;

    void *pYv,*pXv,*pHv,*pZv,*pWpv,*pScv,*pShv;
    cudaGetSymbolAddress(&pYv, g_Ybuf);
    cudaGetSymbolAddress(&pXv, g_Xbuf);
    cudaGetSymbolAddress(&pHv, g_Hbuf);
    cudaGetSymbolAddress(&pZv, g_Zbuf);
    cudaGetSymbolAddress(&pWpv,g_Wp);
    cudaGetSymbolAddress(&pScv,g_scaleL);
    cudaGetSymbolAddress(&pShv,g_shiftL);
    float* pY=(float*)pYv; float* pX=(float*)pXv; float* pH=(float*)pHv;
    float* pZ=(float*)pZv; float* pWp=(float*)pWpv;
    float* scL=(float*)pScv; float* shL=(float*)pShv;

    cudaFuncSetAttribute(fps_kernel, cudaFuncAttributeMaxDynamicSharedMemorySize, 3*8192*8);

    transpose_pts<<<dim3(N_/32, C_/32, B_), dim3(32,32)>>>(pts);
    pnorm_kernel<<<(B_*N_+1023)/1024,1024>>>(xyz);
    wpad_kernel<<<(CO_*KP0_+1023)/1024,1024>>>(wproj);

    fps_kernel<<<B_,512,3*8192*8>>>(xyz,out);
    query_kernel<<<(B_*S_*32)/256,256>>>(xyz);

    const int GG=M_/128;

    gemm_kernel<KP0_,2><<<GG,256>>>(pY, pWp, pY, xyz, scL, shL, nullptr, nullptr, nullptr);
    finalize_kernel<<<1,128>>>(gproj, bproj, scL+0*CO_, shL+0*CO_);

    gemm_kernel<128,1><<<GG,256>>>(pY, w1, pH, xyz, scL+0*CO_, shL+0*CO_, nullptr, nullptr, nullptr);
    finalize_kernel<<<1,128>>>(g1, b1, scL+1*CO_, shL+1*CO_);
    gemm_kernel<128,1><<<GG,256>>>(pH, w2, pX, xyz, scL+1*CO_, shL+1*CO_, nullptr, nullptr, nullptr);
    finalize_kernel<<<1,128>>>(g2, b2, scL+2*CO_, shL+2*CO_);

    gemm_kernel<128,3><<<GG,256>>>(pX, w1+CO_*CO_, pZ, xyz,
                                   scL+2*CO_, shL+2*CO_, pY, scL+0*CO_, shL+0*CO_);
    finalize_kernel<<<1,128>>>(g1+CO_, b1+CO_, scL+3*CO_, shL+3*CO_);
    gemm_kernel<128,1><<<GG,256>>>(pZ, w2+CO_*CO_, pH, xyz, scL+3*CO_, shL+3*CO_, nullptr, nullptr, nullptr);
    finalize_kernel<<<1,128>>>(g2+CO_, b2+CO_, scL+4*CO_, shL+4*CO_);

    maxpool3_kernel<<<(B_*S_*CO_)/256,256>>>(pH, pX, pY, out + B_*3*S_, scL, shL);
}

// round 16
// speedup vs baseline: 1.8286x; 1.1129x over previous
#include <cuda_runtime.h>
#include <cuda_bf16.h>
#include <cstdint>

#define B_   4
#define N_   16384
#define C_   64
#define S_   2048
#define K_   32
#define M_   (B_*S_*K_)
#define CO_  128
#define KP0_ 80

#define PACK_F32X2(out, lo, hi) \
    asm("mov.b64 %0, {%1, %2};" : "=l"(out) : "f"(lo), "f"(hi))
#define UNPACK_F32X2(lo, hi, in) \
    asm("mov.b64 {%0, %1}, %2;" : "=f"(lo), "=f"(hi) : "l"(in))
#define ADD_F32X2(out, a, b) \
    asm("add.rn.f32x2 %0, %1, %2;" : "=l"(out) : "l"(a), "l"(b))
#define MUL_F32X2(out, a, b) \
    asm("mul.rn.f32x2 %0, %1, %2;" : "=l"(out) : "l"(a), "l"(b))
#define FMA_F32X2(out, a, b, c) \
    asm("fma.rn.f32x2 %0, %1, %2, %3;" : "=l"(out) : "l"(a), "l"(b), "l"(c))
#define REDUX_MAX_U32(out, in) \
    asm("redux.sync.max.u32 %0, %1, 0xffffffff;" : "=r"(out) : "r"(in))
#define REDUX_MIN_U32(out, in) \
    asm("redux.sync.min.u32 %0, %1, 0xffffffff;" : "=r"(out) : "r"(in))

typedef unsigned long long u64;
typedef unsigned int u32;

__device__ __align__(16) float g_newxyz[B_*S_*3];
__device__ int   g_idx[B_*S_*K_];
__device__ __align__(16) float g_ptsT[(size_t)B_*N_*C_];
__device__ float g_pnorm[B_*N_];
__device__ __align__(16) float g_Ybuf[(size_t)M_*CO_];
__device__ __align__(16) float g_Xbuf[(size_t)M_*CO_];
__device__ __align__(16) float g_Hbuf[(size_t)M_*CO_];
__device__ __align__(16) float g_Zbuf[(size_t)M_*CO_];
__device__ __align__(16) float g_Wp[CO_*KP0_];
__device__ __align__(16) float g_sum[CO_];
__device__ __align__(16) float g_sq[CO_];
__device__ __align__(16) float g_scaleL[5*CO_];
__device__ __align__(16) float g_shiftL[5*CO_];

__device__ __forceinline__ void mma_bf16(float* d, u32 a0,u32 a1,u32 a2,u32 a3, u32 b0,u32 b1){
    asm("mma.sync.aligned.m16n8k16.row.col.f32.bf16.bf16.f32 "
        "{%0,%1,%2,%3},{%4,%5,%6,%7},{%8,%9},{%0,%1,%2,%3};"
        : "+f"(d[0]),"+f"(d[1]),"+f"(d[2]),"+f"(d[3])
        : "r"(a0),"r"(a1),"r"(a2),"r"(a3),"r"(b0),"r"(b1));
}
__device__ __forceinline__ void split_bf16(float e, float o, u32& hi, u32& lo){
    __nv_bfloat162 h2=__floats2bfloat162_rn(e,o);
    hi=*reinterpret_cast<u32*>(&h2);
    float ef=__uint_as_float(hi<<16);
    float of=__uint_as_float(hi&0xffff0000u);
    __nv_bfloat162 l2=__floats2bfloat162_rn(e-ef,o-of);
    lo=*reinterpret_cast<u32*>(&l2);
}

// FPS (blocks 0..3) + overlapped prep (blocks 4..147): transpose, pnorm, wpad+stats-zero.
__global__ void __launch_bounds__(512,1) fps_kernel(const float* __restrict__ xyz,
                                                    float* __restrict__ out0,
                                                    const float* __restrict__ pts,
                                                    const float* __restrict__ wproj){
    extern __shared__ u64 fsmu[];
    const int t=threadIdx.x;

    if(blockIdx.x>=B_){
        // ---------------- prep blocks ----------------
        const int pb=blockIdx.x-B_;         // 0..143
        const int NP=144;
        // pnorm
        for(int id=pb*512+t; id<B_*N_; id+=NP*512){
            int b=id/N_, n=id%N_;
            const float* Xp=xyz+(size_t)b*3*N_;
            float x=Xp[n], y=Xp[N_+n], z=Xp[2*N_+n];
            g_pnorm[id]=fmaf(z,z,fmaf(x,x,y*y));
        }
        // wpad + stats zero
        if(pb==0 && t<CO_){ g_sum[t]=0.f; g_sq[t]=0.f; }
        for(int id=pb*512+t; id<CO_*KP0_; id+=NP*512){
            int o=id/KP0_, k=id%KP0_;
            g_Wp[id]=(k<67)?wproj[o*67+k]:0.0f;
        }
        // transpose pts -> ptsT, 32x32 tiles, 512 threads (each 2 rows)
        float* tile=reinterpret_cast<float*>(fsmu);   // 32*33 floats
        const int tx=t&31, ty=t>>5;                   // ty 0..15
        for(int tl=pb; tl<4096; tl+=NP){
            int b=tl>>10, rem=tl&1023;
            int nblk=rem&511, cblk=rem>>9;
            int n0=nblk<<5, c0=cblk<<5;
            tile[ty*33+tx]     =pts[((size_t)b*C_+(c0+ty))*N_+n0+tx];
            tile[(ty+16)*33+tx]=pts[((size_t)b*C_+(c0+ty+16))*N_+n0+tx];
            __syncthreads();
            g_ptsT[((size_t)b*N_+(n0+ty))*C_+c0+tx]   =tile[tx*33+ty];
            g_ptsT[((size_t)b*N_+(n0+ty+16))*C_+c0+tx]=tile[tx*33+ty+16];
            __syncthreads();
        }
        return;
    }

    // ---------------- FPS blocks ----------------
    const int b=blockIdx.x;
    const float* Xp=xyz+(size_t)b*3*N_;
    u64* sxu=fsmu;
    u64* syu=fsmu+8192;
    u64* szu=fsmu+16384;
    __shared__ int s_bmax[2];
    __shared__ int s_win[2];

    u64 rx[8], ry[8], rz[8];
    u64 qx[4], qy[4];
    float dmin[32];
#pragma unroll
    for(int j=0;j<16;j++){
        int n=j*512+t;
        float x0=Xp[n],        x1=Xp[n+8192];
        float y0=Xp[N_+n],     y1=Xp[N_+n+8192];
        float z0=Xp[2*N_+n],   z1=Xp[2*N_+n+8192];
        u64 px,py,pz;
        PACK_F32X2(px,x0,x1); PACK_F32X2(py,y0,y1); PACK_F32X2(pz,z0,z1);
        sxu[n]=px; syu[n]=py; szu[n]=pz;
        if(j<8){ rx[j]=px; ry[j]=py; rz[j]=pz; }
        else if(j<12){ qx[j-8]=px; qy[j-8]=py; }
        dmin[2*j]=1e10f; dmin[2*j+1]=1e10f;
    }
    float cx=Xp[0], cy=Xp[N_], cz=Xp[2*N_];
    if(t==0){
        out0[(size_t)b*3*S_+0]      =cx;
        out0[(size_t)b*3*S_+S_+0]   =cy;
        out0[(size_t)b*3*S_+2*S_+0] =cz;
        float* nz=g_newxyz+(size_t)b*S_*3;
        nz[0]=cx; nz[1]=cy; nz[2]=cz;
        s_bmax[0]=0; s_bmax[1]=0;
        s_win[0]=0x7fffffff; s_win[1]=0x7fffffff;
    }
    __syncthreads();

    const int lane=t&31;
    int p=0;
    for(int it=0; it<S_-1; ++it){
        float ncx=-cx, ncy=-cy, ncz=-cz;
        u64 ncx2,ncy2,ncz2;
        PACK_F32X2(ncx2,ncx,ncx); PACK_F32X2(ncy2,ncy,ncy); PACK_F32X2(ncz2,ncz,ncz);
        float bv=0.0f;
#pragma unroll
        for(int j=0;j<8;j++){
            u64 dx,dy,dz,tt,dd;
            ADD_F32X2(dx,rx[j],ncx2);
            ADD_F32X2(dy,ry[j],ncy2);
            ADD_F32X2(dz,rz[j],ncz2);
            MUL_F32X2(tt,dy,dy);
            FMA_F32X2(tt,dx,dx,tt);
            FMA_F32X2(dd,dz,dz,tt);
            float d0,d1; UNPACK_F32X2(d0,d1,dd);
            float m0=fminf(dmin[2*j],d0);   dmin[2*j]=m0;
            float m1=fminf(dmin[2*j+1],d1); dmin[2*j+1]=m1;
            bv=fmaxf(bv,m0); bv=fmaxf(bv,m1);
        }
#pragma unroll
        for(int j=8;j<12;j++){
            int n=j*512+t;
            u64 dx,dy,dz,tt,dd;
            ADD_F32X2(dx,qx[j-8],ncx2);
            ADD_F32X2(dy,qy[j-8],ncy2);
            ADD_F32X2(dz,szu[n],ncz2);
            MUL_F32X2(tt,dy,dy);
            FMA_F32X2(tt,dx,dx,tt);
            FMA_F32X2(dd,dz,dz,tt);
            float d0,d1; UNPACK_F32X2(d0,d1,dd);
            float m0=fminf(dmin[2*j],d0);   dmin[2*j]=m0;
            float m1=fminf(dmin[2*j+1],d1); dmin[2*j+1]=m1;
            bv=fmaxf(bv,m0); bv=fmaxf(bv,m1);
        }
#pragma unroll
        for(int j=12;j<16;j++){
            int n=j*512+t;
            u64 dx,dy,dz,tt,dd;
            ADD_F32X2(dx,sxu[n],ncx2);
            ADD_F32X2(dy,syu[n],ncy2);
            ADD_F32X2(dz,szu[n],ncz2);
            MUL_F32X2(tt,dy,dy);
            FMA_F32X2(tt,dx,dx,tt);
            FMA_F32X2(dd,dz,dz,tt);
            float d0,d1; UNPACK_F32X2(d0,d1,dd);
            float m0=fminf(dmin[2*j],d0);   dmin[2*j]=m0;
            float m1=fminf(dmin[2*j+1],d1); dmin[2*j+1]=m1;
            bv=fmaxf(bv,m0); bv=fmaxf(bv,m1);
        }
        u32 wmax;
        REDUX_MAX_U32(wmax, __float_as_uint(bv));
        if(lane==0) atomicMax(&s_bmax[p], (int)wmax);
        __syncthreads();
        const float bmax=__int_as_float(s_bmax[p]);
        if(__uint_as_float(wmax)==bmax){      // warp-uniform
            int cand=0x7fffffff;
#pragma unroll
            for(int k=0;k<32;k++){
                int idx=(k>>1)*512+t+((k&1)<<13);
                if(dmin[k]==bmax) cand=min(cand,idx);
            }
            u32 cm;
            REDUX_MIN_U32(cm,(u32)cand);
            if(lane==0) atomicMin(&s_win[p],(int)cm);
        }
        __syncthreads();
        const int w=s_win[p];
        int n=w&8191, hi=w>>13;
        float a0,a1;
        UNPACK_F32X2(a0,a1,sxu[n]); cx = hi? a1:a0;
        UNPACK_F32X2(a0,a1,syu[n]); cy = hi? a1:a0;
        UNPACK_F32X2(a0,a1,szu[n]); cz = hi? a1:a0;
        if(t==0){ s_bmax[p^1]=0; s_win[p^1]=0x7fffffff; }
        if(t==32){
            out0[(size_t)b*3*S_+(it+1)]       =cx;
            out0[(size_t)b*3*S_+S_+(it+1)]    =cy;
            out0[(size_t)b*3*S_+2*S_+(it+1)]  =cz;
            float* nz=g_newxyz+((size_t)b*S_+(it+1))*3;
            nz[0]=cx; nz[1]=cy; nz[2]=cz;
        }
        p^=1;
    }
}

__global__ void query_kernel(const float* __restrict__ xyz){
    int gw=(blockIdx.x*blockDim.x+threadIdx.x)>>5;
    int lane=threadIdx.x&31;
    if(gw>=B_*S_) return;
    int b=gw/S_;
    const float* nz=g_newxyz+(size_t)gw*3;
    float cx=nz[0],cy=nz[1],cz=nz[2];
    float srcn=fmaf(cz,cz,fmaf(cx,cx,cy*cy));
    const float* Xp=xyz+(size_t)b*3*N_;
    const float* pn=g_pnorm+(size_t)b*N_;
    int* dst=g_idx+(size_t)gw*K_;
    int count=0, first=0; bool haveFirst=false;
    for(int base=0; base<N_; base+=32){
        int n=base+lane;
        float dot=fmaf(cz,Xp[2*N_+n],fmaf(cy,Xp[N_+n],cx*Xp[n]));
        float d=fmaf(-2.0f,dot,srcn)+pn[n];
        bool ok=!(d>0.04f);
        unsigned m=__ballot_sync(0xffffffffu,ok);
        if(m){
            if(!haveFirst){first=base+__ffs(m)-1; haveFirst=true;}
            int rank=__popc(m&((1u<<lane)-1u));
            if(ok&&(count+rank)<K_) dst[count+rank]=n;
            count+=__popc(m);
            if(count>=K_) break;
        }
    }
    if(count<K_){
        for(int sl=count+lane; sl<K_; sl+=32) dst[sl]=first;
    }
}

// 3xBF16 tensor-core GEMM (m16n8k16). MODE: 0=raw A, 1=bn+relu on A,
// 2=gather-build A, 3=A=relu(bnA(a)+relu(bnB(a0))). Fused BN stats.
#define BKP2 136
template<int K, int MODE>
__global__ void __launch_bounds__(256,2) gemm_kernel(const float* __restrict__ A,
                                                     const float* __restrict__ W,
                                                     float* __restrict__ Y,
                                                     const float* __restrict__ xyz,
                                                     const float* __restrict__ scA,
                                                     const float* __restrict__ shA,
                                                     const float* __restrict__ A0,
                                                     const float* __restrict__ scB,
                                                     const float* __restrict__ shB){
    __shared__ u32 Abh[2][8][BKP2];
    __shared__ u32 Abl[2][8][BKP2];
    __shared__ u32 Bbh[2][8][BKP2];
    __shared__ u32 Bbl[2][8][BKP2];
    __shared__ float sred[256];
    const int tid=threadIdx.x, m0=blockIdx.x<<7;
    const int lrow=tid>>1, lcol=(tid&1)<<3;
    const int row=m0+lrow;
    const int wid=tid>>5, lane=tid&31;
    const int wm=(wid&3)<<5, wn=(wid>>2)<<6;
    const int g=lane>>2, tg=lane&3;

    sred[tid]=0.f;

    const float* gsrc=nullptr; const float* xp=nullptr;
    float ncx=0.f,ncy=0.f,ncz=0.f; int jj=0;
    if(MODE==2){
        jj=g_idx[row];
        int bidx=row>>16;
        int cent=row>>5;
        ncx=g_newxyz[cent*3+0]; ncy=g_newxyz[cent*3+1]; ncz=g_newxyz[cent*3+2];
        gsrc=g_ptsT+((size_t)bidx*N_+jj)*C_;
        xp=xyz+(size_t)bidx*3*N_;
    }
    const float* Aptr=A+(size_t)row*K+lcol;
    const float* A0ptr=(MODE==3)? A0+(size_t)row*K+lcol : nullptr;
    const float* Wptr=W+(size_t)lrow*K+lcol;

    auto loadA4=[&](int k0,int off)->float4{
        if(MODE==2){
            float v[4];
#pragma unroll
            for(int q=0;q<4;q++){
                int c=k0+lcol+off+q;
                float t;
                if(c<3){ float nn=(c==0)?ncx:((c==1)?ncy:ncz); t=xp[(size_t)c*N_+jj]-nn; }
                else if(c<67) t=gsrc[c-3];
                else t=0.f;
                v[q]=t;
            }
            return make_float4(v[0],v[1],v[2],v[3]);
        }else{
            float4 a=*reinterpret_cast<const float4*>(Aptr+k0+off);
            if(MODE==1){
                int c=k0+lcol+off;
                float4 sc=*reinterpret_cast<const float4*>(&scA[c]);
                float4 sh=*reinterpret_cast<const float4*>(&shA[c]);
                a.x=fmaxf(0.f,fmaf(a.x,sc.x,sh.x));
                a.y=fmaxf(0.f,fmaf(a.y,sc.y,sh.y));
                a.z=fmaxf(0.f,fmaf(a.z,sc.z,sh.z));
                a.w=fmaxf(0.f,fmaf(a.w,sc.w,sh.w));
            }else if(MODE==3){
                int c=k0+lcol+off;
                float4 a0=*reinterpret_cast<const float4*>(A0ptr+k0+off);
                float4 sc=*reinterpret_cast<const float4*>(&scA[c]);
                float4 sh=*reinterpret_cast<const float4*>(&shA[c]);
                float4 s0=*reinterpret_cast<const float4*>(&scB[c]);
                float4 h0=*reinterpret_cast<const float4*>(&shB[c]);
                float x0=fmaxf(0.f,fmaf(a0.x,s0.x,h0.x));
                float x1=fmaxf(0.f,fmaf(a0.y,s0.y,h0.y));
                float x2=fmaxf(0.f,fmaf(a0.z,s0.z,h0.z));
                float x3=fmaxf(0.f,fmaf(a0.w,s0.w,h0.w));
                a.x=fmaxf(0.f,fmaf(a.x,sc.x,sh.x)+x0);
                a.y=fmaxf(0.f,fmaf(a.y,sc.y,sh.y)+x1);
                a.z=fmaxf(0.f,fmaf(a.z,sc.z,sh.z)+x2);
                a.w=fmaxf(0.f,fmaf(a.w,sc.w,sh.w)+x3);
            }
            return a;
        }
    };

    auto stage=[&](int buf, float4 a0v, float4 a1v, float4 w0v, float4 w1v){
        const int kp0=lcol>>1;
        u32 h,l;
        split_bf16(a0v.x,a0v.y,h,l); Abh[buf][kp0  ][lrow]=h; Abl[buf][kp0  ][lrow]=l;
        split_bf16(a0v.z,a0v.w,h,l); Abh[buf][kp0+1][lrow]=h; Abl[buf][kp0+1][lrow]=l;
        split_bf16(a1v.x,a1v.y,h,l); Abh[buf][kp0+2][lrow]=h; Abl[buf][kp0+2][lrow]=l;
        split_bf16(a1v.z,a1v.w,h,l); Abh[buf][kp0+3][lrow]=h; Abl[buf][kp0+3][lrow]=l;
        split_bf16(w0v.x,w0v.y,h,l); Bbh[buf][kp0  ][lrow]=h; Bbl[buf][kp0  ][lrow]=l;
        split_bf16(w0v.z,w0v.w,h,l); Bbh[buf][kp0+1][lrow]=h; Bbl[buf][kp0+1][lrow]=l;
        split_bf16(w1v.x,w1v.y,h,l); Bbh[buf][kp0+2][lrow]=h; Bbl[buf][kp0+2][lrow]=l;
        split_bf16(w1v.z,w1v.w,h,l); Bbh[buf][kp0+3][lrow]=h; Bbl[buf][kp0+3][lrow]=l;
    };

    float d[2][8][4];
#pragma unroll
    for(int mt=0;mt<2;mt++)
#pragma unroll
        for(int nt=0;nt<8;nt++)
#pragma unroll
            for(int q=0;q<4;q++) d[mt][nt][q]=0.f;

    constexpr int NT=K/16;
    float4 a0v=loadA4(0,0), a1v=loadA4(0,4);
    float4 w0v=*reinterpret_cast<const float4*>(Wptr);
    float4 w1v=*reinterpret_cast<const float4*>(Wptr+4);
    stage(0,a0v,a1v,w0v,w1v);
    __syncthreads();

    for(int it=0; it<NT; ++it){
        const int cur=it&1;
        if(it+1<NT){
            a0v=loadA4((it+1)*16,0); a1v=loadA4((it+1)*16,4);
            w0v=*reinterpret_cast<const float4*>(Wptr+(it+1)*16);
            w1v=*reinterpret_cast<const float4*>(Wptr+(it+1)*16+4);
        }
        u32 ah[2][4], al[2][4];
#pragma unroll
        for(int mt=0;mt<2;mt++){
            int r0=wm+(mt<<4)+g;
            ah[mt][0]=Abh[cur][tg  ][r0];
            ah[mt][1]=Abh[cur][tg  ][r0+8];
            ah[mt][2]=Abh[cur][tg+4][r0];
            ah[mt][3]=Abh[cur][tg+4][r0+8];
            al[mt][0]=Abl[cur][tg  ][r0];
            al[mt][1]=Abl[cur][tg  ][r0+8];
            al[mt][2]=Abl[cur][tg+4][r0];
            al[mt][3]=Abl[cur][tg+4][r0+8];
        }
#pragma unroll
        for(int nt=0;nt<8;nt++){
            int nn=wn+(nt<<3)+g;
            u32 bh0=Bbh[cur][tg  ][nn];
            u32 bh1=Bbh[cur][tg+4][nn];
            u32 bl0=Bbl[cur][tg  ][nn];
            u32 bl1=Bbl[cur][tg+4][nn];
#pragma unroll
            for(int mt=0;mt<2;mt++){
                mma_bf16(d[mt][nt], ah[mt][0],ah[mt][1],ah[mt][2],ah[mt][3], bh0,bh1);
                mma_bf16(d[mt][nt], ah[mt][0],ah[mt][1],ah[mt][2],ah[mt][3], bl0,bl1);
                mma_bf16(d[mt][nt], al[mt][0],al[mt][1],al[mt][2],al[mt][3], bh0,bh1);
            }
        }
        if(it+1<NT) stage(cur^1,a0v,a1v,w0v,w1v);
        __syncthreads();
    }

    float cs[8][2], cq[8][2];
#pragma unroll
    for(int nt=0;nt<8;nt++){ cs[nt][0]=0.f; cs[nt][1]=0.f; cq[nt][0]=0.f; cq[nt][1]=0.f; }
#pragma unroll
    for(int nt=0;nt<8;nt++){
        int nbase=wn+(nt<<3)+(tg<<1);
#pragma unroll
        for(int mt=0;mt<2;mt++){
            int mlo=m0+wm+(mt<<4)+g;
            float d0=d[mt][nt][0], d1=d[mt][nt][1], d2=d[mt][nt][2], d3=d[mt][nt][3];
            *reinterpret_cast<float2*>(&Y[(size_t)mlo*CO_+nbase])    =make_float2(d0,d1);
            *reinterpret_cast<float2*>(&Y[(size_t)(mlo+8)*CO_+nbase])=make_float2(d2,d3);
            cs[nt][0]+=d0+d2; cs[nt][1]+=d1+d3;
            cq[nt][0]=fmaf(d0,d0,cq[nt][0]); cq[nt][0]=fmaf(d2,d2,cq[nt][0]);
            cq[nt][1]=fmaf(d1,d1,cq[nt][1]); cq[nt][1]=fmaf(d3,d3,cq[nt][1]);
        }
    }
#pragma unroll
    for(int off=4; off<32; off<<=1){
#pragma unroll
        for(int nt=0;nt<8;nt++){
            cs[nt][0]+=__shfl_xor_sync(0xffffffffu,cs[nt][0],off);
            cs[nt][1]+=__shfl_xor_sync(0xffffffffu,cs[nt][1],off);
            cq[nt][0]+=__shfl_xor_sync(0xffffffffu,cq[nt][0],off);
            cq[nt][1]+=__shfl_xor_sync(0xffffffffu,cq[nt][1],off);
        }
    }
    if(lane<4){
#pragma unroll
        for(int nt=0;nt<8;nt++){
            int col=wn+(nt<<3)+(lane<<1);
            atomicAdd(&sred[col],     cs[nt][0]);
            atomicAdd(&sred[col+1],   cs[nt][1]);
            atomicAdd(&sred[128+col],   cq[nt][0]);
            atomicAdd(&sred[128+col+1], cq[nt][1]);
        }
    }
    __syncthreads();
    if(tid<128){
        atomicAdd(&g_sum[tid], sred[tid]);
        atomicAdd(&g_sq[tid],  sred[128+tid]);
    }
}

__global__ void finalize_kernel(const float* __restrict__ gg, const float* __restrict__ bb,
                                float* __restrict__ sc_out, float* __restrict__ sh_out){
    int c=threadIdx.x;
    if(c<CO_){
        const float inv=1.0f/(float)M_;
        float mu=g_sum[c]*inv;
        float var=g_sq[c]*inv-mu*mu;
        float rs=rsqrtf(var+1e-5f);
        float sc=gg[c]*rs;
        sc_out[c]=sc;
        sh_out[c]=bb[c]-mu*sc;
        g_sum[c]=0.f; g_sq[c]=0.f;
    }
}

__global__ void maxpool3_kernel(const float* __restrict__ Y4, const float* __restrict__ Y2,
                                const float* __restrict__ Y0, float* __restrict__ out2,
                                const float* __restrict__ scL, const float* __restrict__ shL){
    int id=blockIdx.x*blockDim.x+threadIdx.x;
    int c=id&127;
    int s=(id>>7)&(S_-1);
    int b=id>>18;
    size_t base=((size_t)(b*S_+s)*K_)*CO_+c;
    float sc0=scL[0*CO_+c], sh0=shL[0*CO_+c];
    float sc2=scL[2*CO_+c], sh2=shL[2*CO_+c];
    float sc4=scL[4*CO_+c], sh4=shL[4*CO_+c];
    float m=-1e30f;
#pragma unroll
    for(int k=0;k<K_;k++){
        size_t o=base+(size_t)k*CO_;
        float x0=fmaxf(0.f,fmaf(Y0[o],sc0,sh0));
        float xr=fmaxf(0.f,fmaf(Y2[o],sc2,sh2)+x0);
        float v =fmaxf(0.f,fmaf(Y4[o],sc4,sh4)+xr);
        m=fmaxf(m,v);
    }
    out2[((size_t)b*CO_+c)*S_+s]=m;
}

extern "C" void kernel_launch(void* const* d_in, const int* in_sizes, int n_in,
                              void* d_out, int out_size){
    const float* xyz  =(const float*)d_in[0];
    const float* pts  =(const float*)d_in[1];
    const float* wproj=(const float*)d_in[2];
    const float* gproj=(const float*)d_in[3];
    const float* bproj=(const float*)d_in[4];
    const float* w1   =(const float*)d_in[5];
    const float* w2   =(const float*)d_in[6];
    const float* g1   =(const float*)d_in[7];
    const float* b1   =(const float*)d_in[8];
    const float* g2   =(const float*)d_in[9];
    const float* b2   =(const float*)d_in[10];
    float* out=(float*)d_out;

    void *pYv,*pXv,*pHv,*pZv,*pWpv,*pScv,*pShv;
    cudaGetSymbolAddress(&pYv, g_Ybuf);
    cudaGetSymbolAddress(&pXv, g_Xbuf);
    cudaGetSymbolAddress(&pHv, g_Hbuf);
    cudaGetSymbolAddress(&pZv, g_Zbuf);
    cudaGetSymbolAddress(&pWpv,g_Wp);
    cudaGetSymbolAddress(&pScv,g_scaleL);
    cudaGetSymbolAddress(&pShv,g_shiftL);
    float* pY=(float*)pYv; float* pX=(float*)pXv; float* pH=(float*)pHv;
    float* pZ=(float*)pZv; float* pWp=(float*)pWpv;
    float* scL=(float*)pScv; float* shL=(float*)pShv;

    cudaFuncSetAttribute(fps_kernel, cudaFuncAttributeMaxDynamicSharedMemorySize, 3*8192*8);

    fps_kernel<<<B_+144,512,3*8192*8>>>(xyz,out,pts,wproj);
    query_kernel<<<(B_*S_*32)/256,256>>>(xyz);

    const int GG=M_/128;

    gemm_kernel<KP0_,2><<<GG,256>>>(pY, pWp, pY, xyz, scL, shL, nullptr, nullptr, nullptr);
    finalize_kernel<<<1,128>>>(gproj, bproj, scL+0*CO_, shL+0*CO_);

    gemm_kernel<128,1><<<GG,256>>>(pY, w1, pH, xyz, scL+0*CO_, shL+0*CO_, nullptr, nullptr, nullptr);
    finalize_kernel<<<1,128>>>(g1, b1, scL+1*CO_, shL+1*CO_);
    gemm_kernel<128,1><<<GG,256>>>(pH, w2, pX, xyz, scL+1*CO_, shL+1*CO_, nullptr, nullptr, nullptr);
    finalize_kernel<<<1,128>>>(g2, b2, scL+2*CO_, shL+2*CO_);

    gemm_kernel<128,3><<<GG,256>>>(pX, w1+CO_*CO_, pZ, xyz,
                                   scL+2*CO_, shL+2*CO_, pY, scL+0*CO_, shL+0*CO_);
    finalize_kernel<<<1,128>>>(g1+CO_, b1+CO_, scL+3*CO_, shL+3*CO_);
    gemm_kernel<128,1><<<GG,256>>>(pZ, w2+CO_*CO_, pH, xyz, scL+3*CO_, shL+3*CO_, nullptr, nullptr, nullptr);
    finalize_kernel<<<1,128>>>(g2+CO_, b2+CO_, scL+4*CO_, shL+4*CO_);

    maxpool3_kernel<<<(B_*S_*CO_)/256,256>>>(pH, pX, pY, out + B_*3*S_, scL, shL);
}